// round 5
// baseline (speedup 1.0000x reference)
#include <cuda_runtime.h>
#include <math.h>

#define D 256
#define H 8
#define MAXN 50000
#define MAXE 1600000

// -------- scratch (no allocs allowed -> device globals) --------
__device__ float g_q[(size_t)MAXN * D];       // 51.2 MB
__device__ float g_k[(size_t)MAXN * D];       // 51.2 MB
__device__ float g_v[(size_t)MAXN * D];       // 51.2 MB
__device__ float g_attn[(size_t)MAXN * D];    // 51.2 MB
__device__ float g_s[(size_t)MAXE * H];       // 51.2 MB (CSR-ordered scores)
__device__ int   g_cnt[MAXN];
__device__ int   g_ptr[MAXN + 1];
__device__ int   g_fill[MAXN];
__device__ int   g_colbuf[MAXE];

#define BUF_EXT  0
#define BUF_Q    1
#define BUF_K    2
#define BUF_V    3
#define BUF_ATTN 4

__device__ __forceinline__ float* buf_ptr(int id, float* ext)
{
    switch (id) {
        case BUF_Q:    return g_q;
        case BUF_K:    return g_k;
        case BUF_V:    return g_v;
        case BUF_ATTN: return g_attn;
        default:       return ext;
    }
}

__device__ __forceinline__ unsigned tf32_rna(float x)
{
    unsigned r;
    asm("cvt.rna.tf32.f32 %0, %1;" : "=r"(r) : "f"(x));
    return r;
}

__device__ __forceinline__ void mma_tf32(
    float& c0, float& c1, float& c2, float& c3,
    unsigned a0, unsigned a1, unsigned a2, unsigned a3,
    unsigned b0, unsigned b1)
{
    asm volatile(
        "mma.sync.aligned.m16n8k8.row.col.f32.tf32.tf32.f32 "
        "{%0,%1,%2,%3}, {%4,%5,%6,%7}, {%8,%9}, {%0,%1,%2,%3};\n"
        : "+f"(c0), "+f"(c1), "+f"(c2), "+f"(c3)
        : "r"(a0), "r"(a1), "r"(a2), "r"(a3), "r"(b0), "r"(b1));
}

// ==================== 3xTF32 tensor-core GEMM ====================
// C = alpha * (A @ W + bias).  A: M x 256, W: 256 x 256 row-major.
// BM=128 BN=64 BK=16, 8 warps (4x2), warp tile 32x32.
// A smem [m][20] (pad: (20m+k)%32 unique over 8x4 lane footprint),
// B smem transposed [n][20] (same property) -> conflict-free fragment LDS.
__global__ __launch_bounds__(256) void sgemm_tc_kernel(
    const float* __restrict__ A_ext, int A_id,
    const float* __restrict__ W,
    const float* __restrict__ bias,
    float* __restrict__ C_ext, int C_id,
    int M, float alpha)
{
    const float* A = buf_ptr(A_id, (float*)A_ext);
    float* C = buf_ptr(C_id, C_ext);

    __shared__ unsigned sAh[128][20];
    __shared__ unsigned sAl[128][20];
    __shared__ unsigned sBh[64][20];
    __shared__ unsigned sBl[64][20];

    const int tid = threadIdx.x;
    const int lane = tid & 31;
    const int warp = tid >> 5;
    const int gid = lane >> 2;    // 0..7
    const int tig = lane & 3;     // 0..3
    const int wm = (warp & 3) * 32;   // warp m offset
    const int wn = (warp >> 2) * 32;  // warp n offset
    const int bm = blockIdx.x * 128;
    const int bn = blockIdx.y * 64;

    float acc[2][4][4];
#pragma unroll
    for (int i = 0; i < 2; i++)
#pragma unroll
        for (int j = 0; j < 4; j++)
#pragma unroll
            for (int k = 0; k < 4; k++) acc[i][j][k] = 0.f;

    for (int k0 = 0; k0 < D; k0 += 16) {
        // load A tile 128x16 (2 float4 per thread), split hi/lo
#pragma unroll
        for (int t = 0; t < 2; t++) {
            int s = tid + t * 256;        // 512 float4 slots
            int r = s >> 2;
            int cg = (s & 3) * 4;
            float4 av = make_float4(0.f, 0.f, 0.f, 0.f);
            int gr = bm + r;
            if (gr < M) av = *(const float4*)(A + (size_t)gr * D + k0 + cg);
            float vv[4] = {av.x, av.y, av.z, av.w};
#pragma unroll
            for (int i = 0; i < 4; i++) {
                unsigned hi = tf32_rna(vv[i]);
                unsigned lo = tf32_rna(vv[i] - __uint_as_float(hi));
                sAh[r][cg + i] = hi;
                sAl[r][cg + i] = lo;
            }
        }
        // load W tile 16x64 (1 float4 per thread), transpose into [n][k]
        {
            int r = tid >> 4;             // k row 0..15
            int cg = (tid & 15) * 4;      // n col group
            float4 wv = *(const float4*)(W + (size_t)(k0 + r) * D + bn + cg);
            float vv[4] = {wv.x, wv.y, wv.z, wv.w};
#pragma unroll
            for (int i = 0; i < 4; i++) {
                unsigned hi = tf32_rna(vv[i]);
                unsigned lo = tf32_rna(vv[i] - __uint_as_float(hi));
                sBh[cg + i][r] = hi;
                sBl[cg + i][r] = lo;
            }
        }
        __syncthreads();

#pragma unroll
        for (int ks = 0; ks < 2; ks++) {
            const int kb = ks * 8;
            unsigned ah[2][4], al[2][4], bh[4][2], bl[4][2];
#pragma unroll
            for (int ma = 0; ma < 2; ma++) {
                int r0 = wm + ma * 16 + gid;
                ah[ma][0] = sAh[r0][kb + tig];
                ah[ma][1] = sAh[r0 + 8][kb + tig];
                ah[ma][2] = sAh[r0][kb + tig + 4];
                ah[ma][3] = sAh[r0 + 8][kb + tig + 4];
                al[ma][0] = sAl[r0][kb + tig];
                al[ma][1] = sAl[r0 + 8][kb + tig];
                al[ma][2] = sAl[r0][kb + tig + 4];
                al[ma][3] = sAl[r0 + 8][kb + tig + 4];
            }
#pragma unroll
            for (int na = 0; na < 4; na++) {
                int n0 = wn + na * 8 + gid;
                bh[na][0] = sBh[n0][kb + tig];
                bh[na][1] = sBh[n0][kb + tig + 4];
                bl[na][0] = sBl[n0][kb + tig];
                bl[na][1] = sBl[n0][kb + tig + 4];
            }
#pragma unroll
            for (int ma = 0; ma < 2; ma++)
#pragma unroll
                for (int na = 0; na < 4; na++) {
                    float* c = acc[ma][na];
                    mma_tf32(c[0], c[1], c[2], c[3],
                             ah[ma][0], ah[ma][1], ah[ma][2], ah[ma][3],
                             bh[na][0], bh[na][1]);
                    mma_tf32(c[0], c[1], c[2], c[3],
                             al[ma][0], al[ma][1], al[ma][2], al[ma][3],
                             bh[na][0], bh[na][1]);
                    mma_tf32(c[0], c[1], c[2], c[3],
                             ah[ma][0], ah[ma][1], ah[ma][2], ah[ma][3],
                             bl[na][0], bl[na][1]);
                }
        }
        __syncthreads();
    }

    // epilogue
#pragma unroll
    for (int ma = 0; ma < 2; ma++) {
        int gr0 = bm + wm + ma * 16 + gid;
        int gr1 = gr0 + 8;
#pragma unroll
        for (int na = 0; na < 4; na++) {
            int gc = bn + wn + na * 8 + tig * 2;
            float b0 = bias[gc], b1 = bias[gc + 1];
            float* c = acc[ma][na];
            if (gr0 < M) {
                float2 o = make_float2((c[0] + b0) * alpha, (c[1] + b1) * alpha);
                *(float2*)(C + (size_t)gr0 * D + gc) = o;
            }
            if (gr1 < M) {
                float2 o = make_float2((c[2] + b0) * alpha, (c[3] + b1) * alpha);
                *(float2*)(C + (size_t)gr1 * D + gc) = o;
            }
        }
    }
}

// ==================== CSR build ====================
__global__ void zero_kernel(int n)
{
    int i = blockIdx.x * blockDim.x + threadIdx.x;
    if (i < n) g_cnt[i] = 0;
}

__global__ void hist_kernel(const int* __restrict__ row, int E)
{
    int e = blockIdx.x * blockDim.x + threadIdx.x;
    if (e < E) atomicAdd(&g_cnt[row[e]], 1);
}

__global__ void scan_kernel(int n)
{
    __shared__ int warp_sums[32];
    __shared__ int carry;
    const int tid = threadIdx.x;
    const int lane = tid & 31;
    const int wid = tid >> 5;
    if (tid == 0) carry = 0;
    __syncthreads();
    for (int base = 0; base < n; base += 1024) {
        int i = base + tid;
        int v = (i < n) ? g_cnt[i] : 0;
        int x = v;
#pragma unroll
        for (int d = 1; d < 32; d <<= 1) {
            int y = __shfl_up_sync(0xffffffffu, x, d);
            if (lane >= d) x += y;
        }
        if (lane == 31) warp_sums[wid] = x;
        __syncthreads();
        if (wid == 0) {
            int sv = warp_sums[lane];
#pragma unroll
            for (int d = 1; d < 32; d <<= 1) {
                int y = __shfl_up_sync(0xffffffffu, sv, d);
                if (lane >= d) sv += y;
            }
            warp_sums[lane] = sv;
        }
        __syncthreads();
        int prefix = (wid > 0) ? warp_sums[wid - 1] : 0;
        int excl = x - v + prefix + carry;
        if (i < n) { g_ptr[i] = excl; g_fill[i] = excl; }
        int total = warp_sums[31];
        __syncthreads();
        if (tid == 0) carry = carry + total;
        __syncthreads();
    }
    if (tid == 0) g_ptr[n] = carry;
}

__global__ void scatter_kernel(const int* __restrict__ row,
                               const int* __restrict__ col, int E)
{
    int e = blockIdx.x * blockDim.x + threadIdx.x;
    if (e < E) {
        int p = atomicAdd(&g_fill[row[e]], 1);
        g_colbuf[p] = col[e];
    }
}

// ==================== per-node attention: 1 warp / node ====================
__global__ __launch_bounds__(256) void attn_kernel(int nnodes)
{
    const int lane = threadIdx.x & 31;
    const int node = blockIdx.x * 8 + (threadIdx.x >> 5);
    if (node >= nnodes) return;
    const int start = g_ptr[node];
    const int end = g_ptr[node + 1];

    const int b4 = (lane >> 4) & 1;
    const int b3 = (lane >> 3) & 1;
    const int b2 = (lane >> 2) & 1;
    const int myh = (b2 << 2) | (b3 << 1) | b4;
    const int hh = lane & 7;
    const int owner = ((hh & 1) << 4) | (((hh >> 1) & 1) << 3) | (((hh >> 2) & 1) << 2);

    const float4* qp = (const float4*)(g_q + (size_t)node * D + lane * 8);
    float4 q0 = qp[0], q1 = qp[1];

    float m_local = -1e30f;

    // ---- phase 1: scores + per-head max ----
    for (int base = start; base < end; base += 32) {
        int myj = 0;
        if (base + lane < end) myj = g_colbuf[base + lane];
        int cnt = min(32, end - base);
        for (int t = 0; t < cnt; t++) {
            int j = __shfl_sync(0xffffffffu, myj, t);
            const float4* kp = (const float4*)(g_k + (size_t)j * D + lane * 8);
            float4 k0 = kp[0], k1 = kp[1];
            float p0 = q0.x * k0.x, p1 = q0.y * k0.y, p2 = q0.z * k0.z, p3 = q0.w * k0.w;
            float p4 = q1.x * k1.x, p5 = q1.y * k1.y, p6 = q1.z * k1.z, p7 = q1.w * k1.w;
            float keep, send;
            keep = b4 ? p1 : p0; send = b4 ? p0 : p1;
            float tA0 = keep + __shfl_xor_sync(0xffffffffu, send, 16);
            keep = b4 ? p3 : p2; send = b4 ? p2 : p3;
            float tA1 = keep + __shfl_xor_sync(0xffffffffu, send, 16);
            keep = b4 ? p5 : p4; send = b4 ? p4 : p5;
            float tA2 = keep + __shfl_xor_sync(0xffffffffu, send, 16);
            keep = b4 ? p7 : p6; send = b4 ? p6 : p7;
            float tA3 = keep + __shfl_xor_sync(0xffffffffu, send, 16);
            keep = b3 ? tA1 : tA0; send = b3 ? tA0 : tA1;
            float tB0 = keep + __shfl_xor_sync(0xffffffffu, send, 8);
            keep = b3 ? tA3 : tA2; send = b3 ? tA2 : tA3;
            float tB1 = keep + __shfl_xor_sync(0xffffffffu, send, 8);
            keep = b2 ? tB1 : tB0; send = b2 ? tB0 : tB1;
            float s = keep + __shfl_xor_sync(0xffffffffu, send, 4);
            s += __shfl_xor_sync(0xffffffffu, s, 2);
            s += __shfl_xor_sync(0xffffffffu, s, 1);
            m_local = fmaxf(m_local, s);
            if ((lane & 3) == 0)
                g_s[(size_t)(base + t) * H + myh] = s;
        }
    }
    __threadfence_block();
    __syncwarp();

    float m2 = __shfl_sync(0xffffffffu, m_local, owner);

    // ---- phase 2: exp, z, weighted V accumulation ----
    float acc[8];
#pragma unroll
    for (int i = 0; i < 8; i++) acc[i] = 0.f;
    float z = 0.f;

    for (int base = start; base < end; base += 32) {
        int myj = 0;
        if (base + lane < end) myj = g_colbuf[base + lane];
        int cnt = min(32, end - base);
        for (int t = 0; t < cnt; t++) {
            int j = __shfl_sync(0xffffffffu, myj, t);
            float s = g_s[(size_t)(base + t) * H + hh];
            float w = __expf(s - m2);
            z += w;
            const float4* vp = (const float4*)(g_v + (size_t)j * D + lane * 8);
            float4 v0 = vp[0], v1 = vp[1];
            float vr[8] = {v0.x, v0.y, v0.z, v0.w, v1.x, v1.y, v1.z, v1.w};
#pragma unroll
            for (int i = 0; i < 8; i++) {
                float wi = __shfl_sync(0xffffffffu, w, i);
                acc[i] = fmaf(wi, vr[i], acc[i]);
            }
        }
    }
    float invz = (z > 0.f) ? (1.0f / z) : 0.f;
    float out[8];
#pragma unroll
    for (int i = 0; i < 8; i++)
        out[i] = acc[i] * __shfl_sync(0xffffffffu, invz, i);
    float4* op = (float4*)(g_attn + (size_t)node * D + lane * 8);
    op[0] = make_float4(out[0], out[1], out[2], out[3]);
    op[1] = make_float4(out[4], out[5], out[6], out[7]);
}

// ==================== launch ====================
extern "C" void kernel_launch(void* const* d_in, const int* in_sizes, int n_in,
                              void* d_out, int out_size)
{
    const float* x  = (const float*)d_in[0];
    const int*   row = (const int*)d_in[1];
    const int*   col = (const int*)d_in[2];
    const float* Wq = (const float*)d_in[3];
    const float* bq = (const float*)d_in[4];
    const float* Wk = (const float*)d_in[5];
    const float* bk = (const float*)d_in[6];
    const float* Wv = (const float*)d_in[7];
    const float* bv = (const float*)d_in[8];
    const float* Wo = (const float*)d_in[9];
    const float* bo = (const float*)d_in[10];
    float* out = (float*)d_out;

    const int N = in_sizes[0] / D;
    const int E = in_sizes[1];
    const float scaling = 0.17677669529663687f; // 32^-0.5

    // CSR build
    zero_kernel<<<(N + 255) / 256, 256>>>(N);
    hist_kernel<<<(E + 255) / 256, 256>>>(row, E);
    scan_kernel<<<1, 1024>>>(N);
    scatter_kernel<<<(E + 255) / 256, 256>>>(row, col, E);

    // projections on tensor cores (3xTF32); scaling folded into Q
    dim3 ggrid((N + 127) / 128, D / 64);
    sgemm_tc_kernel<<<ggrid, 256>>>(x, BUF_EXT, Wq, bq, nullptr, BUF_Q, N, scaling);
    sgemm_tc_kernel<<<ggrid, 256>>>(x, BUF_EXT, Wk, bk, nullptr, BUF_K, N, 1.f);
    sgemm_tc_kernel<<<ggrid, 256>>>(x, BUF_EXT, Wv, bv, nullptr, BUF_V, N, 1.f);

    // sparse attention (1 warp / node)
    attn_kernel<<<(N + 7) / 8, 256>>>(N);

    // output projection
    sgemm_tc_kernel<<<ggrid, 256>>>(nullptr, BUF_ATTN, Wo, bo, out, BUF_EXT, N, 1.f);
}

// round 8
// speedup vs baseline: 1.3559x; 1.3559x over previous
#include <cuda_runtime.h>
#include <cuda_bf16.h>
#include <math.h>
#include <stdint.h>

#define D 256
#define H 8
#define MAXN 50000
#define MAXE 1600000
#define DP (D / 2)   // 128 k-pairs per row
#define XSP ((size_t)MAXN * DP)   // elements per x-split half

// -------- scratch (no allocs allowed -> device globals) --------
__device__ float g_q[(size_t)MAXN * D];
__device__ float g_k[(size_t)MAXN * D];
__device__ float g_v[(size_t)MAXN * D];
__device__ float g_attn[(size_t)MAXN * D];
// g_s serves two phase-disjoint roles:
//  - during GEMM phases: bf16-pair x-splits (hi at [0,XSP), lo at [XSP,2*XSP))
//  - during attn_kernel: CSR-ordered fp32 scores [E][H]
__device__ float g_s[(size_t)MAXE * H];            // 51.2 MB
__device__ int   g_cnt[MAXN];
__device__ int   g_ptr[MAXN + 1];
__device__ int   g_fill[MAXN];
__device__ int   g_colbuf[MAXE];
__device__ uint32_t g_wth[4][D * DP];   // transposed [n][kpair], hi (0.5 MB ea)
__device__ uint32_t g_wtl[4][D * DP];   // transposed [n][kpair], lo

#define BUF_EXT  0
#define BUF_Q    1
#define BUF_K    2
#define BUF_V    3
#define BUF_ATTN 4

__device__ __forceinline__ float* buf_ptr(int id, float* ext)
{
    switch (id) {
        case BUF_Q:    return g_q;
        case BUF_K:    return g_k;
        case BUF_V:    return g_v;
        case BUF_ATTN: return g_attn;
        default:       return ext;
    }
}

// 2-way bf16 split of a float2 pair (hi = rn(x), lo = rn(x - hi))
__device__ __forceinline__ void split2(float2 a, uint32_t& s1, uint32_t& s2)
{
    __nv_bfloat162 h1 = __float22bfloat162_rn(a);
    float2 f1 = __bfloat1622float2(h1);
    __nv_bfloat162 h2 = __float22bfloat162_rn(make_float2(a.x - f1.x, a.y - f1.y));
    s1 = *(uint32_t*)&h1;
    s2 = *(uint32_t*)&h2;
}

__device__ __forceinline__ void mma_bf16(
    float& c0, float& c1, float& c2, float& c3,
    unsigned a0, unsigned a1, unsigned a2, unsigned a3,
    unsigned b0, unsigned b1)
{
    asm volatile(
        "mma.sync.aligned.m16n8k16.row.col.f32.bf16.bf16.f32 "
        "{%0,%1,%2,%3}, {%4,%5,%6,%7}, {%8,%9}, {%0,%1,%2,%3};\n"
        : "+f"(c0), "+f"(c1), "+f"(c2), "+f"(c3)
        : "r"(a0), "r"(a1), "r"(a2), "r"(a3), "r"(b0), "r"(b1));
}

// ==================== conversion passes ====================
// X (M x 256 fp32) -> x-split halves inside g_s
__global__ __launch_bounds__(256) void convert_x_kernel(
    const float* __restrict__ X_ext, int X_id, int M)
{
    const float* X = buf_ptr(X_id, (float*)X_ext);
    uint32_t* xh = (uint32_t*)g_s;
    uint32_t* xl = (uint32_t*)g_s + XSP;
    int idx = blockIdx.x * blockDim.x + threadIdx.x;   // pair index
    int total = M * DP;
    if (idx < total) {
        float2 v = *(const float2*)(X + (size_t)idx * 2);
        uint32_t h, l;
        split2(v, h, l);
        xh[idx] = h;
        xl[idx] = l;
    }
}

// W (256 x 256 fp32 row-major [k][n]) -> g_wth/g_wtl[widx] as [n][kpair]
__global__ __launch_bounds__(256) void convert_w_kernel(
    const float* __restrict__ W, int widx)
{
    int slot = blockIdx.x * blockDim.x + threadIdx.x;  // kp*256 + n (n fastest)
    if (slot < D * DP) {
        int n = slot & (D - 1);
        int kp = slot >> 8;
        float a0 = W[(size_t)(2 * kp) * D + n];
        float a1 = W[(size_t)(2 * kp + 1) * D + n];
        uint32_t h, l;
        split2(make_float2(a0, a1), h, l);
        g_wth[widx][(size_t)n * DP + kp] = h;
        g_wtl[widx][(size_t)n * DP + kp] = l;
    }
}

// ==================== bf16x3 tensor-core GEMM ====================
// C = alpha * (A @ W + bias).  A pre-split in g_s halves, W pre-split (g_wt*[widx]).
// BM=128 BN=64 BK=32 (16 kpairs), 256 threads, 8 warps (4x2), warp tile 32x32.
// smem stride 20 words: fragment LDS addr = 20*row + c; 20*gid mod 32 spans all
// 4-cosets over the 8x4 lane footprint -> conflict-free.
#define SW 20
__global__ __launch_bounds__(256) void gemm_bf16x3_kernel(
    int widx,
    const float* __restrict__ bias,
    float* __restrict__ C_ext, int C_id,
    int M, float alpha)
{
    float* C = buf_ptr(C_id, C_ext);
    const uint32_t* __restrict__ WTh = g_wth[widx];
    const uint32_t* __restrict__ WTl = g_wtl[widx];
    const uint32_t* __restrict__ xh = (const uint32_t*)g_s;
    const uint32_t* __restrict__ xl = (const uint32_t*)g_s + XSP;

    __shared__ uint32_t sAh[128][SW];
    __shared__ uint32_t sAl[128][SW];
    __shared__ uint32_t sBh[64][SW];
    __shared__ uint32_t sBl[64][SW];

    const int tid = threadIdx.x;
    const int lane = tid & 31;
    const int warp = tid >> 5;
    const int gid = lane >> 2;
    const int tig = lane & 3;
    const int wm = (warp & 3) * 32;
    const int wn = (warp >> 2) * 32;
    const int bm = blockIdx.x * 128;
    const int bn = blockIdx.y * 64;

    float acc[2][4][4];
#pragma unroll
    for (int i = 0; i < 2; i++)
#pragma unroll
        for (int j = 0; j < 4; j++)
#pragma unroll
            for (int k = 0; k < 4; k++) acc[i][j][k] = 0.f;

    for (int k0p = 0; k0p < DP; k0p += 16) {
        // A tile: 128 rows x 16 kpairs, hi+lo
#pragma unroll
        for (int i = 0; i < 8; i++) {
            int slot = tid + i * 256;      // 2048 slots
            int r = slot >> 4;
            int c = slot & 15;
            int gr = bm + r;
            uint32_t vh = 0, vl = 0;
            if (gr < M) {
                size_t gi = (size_t)gr * DP + k0p + c;
                vh = xh[gi];
                vl = xl[gi];
            }
            sAh[r][c] = vh;
            sAl[r][c] = vl;
        }
        // B tile: 64 n-rows x 16 kpairs, hi+lo (already transposed in gmem)
#pragma unroll
        for (int i = 0; i < 4; i++) {
            int slot = tid + i * 256;      // 1024 slots
            int n = slot >> 4;
            int c = slot & 15;
            size_t gi = (size_t)(bn + n) * DP + k0p + c;
            sBh[n][c] = WTh[gi];
            sBl[n][c] = WTl[gi];
        }
        __syncthreads();

#pragma unroll
        for (int ks = 0; ks < 2; ks++) {
            const int kb = ks * 8;
            unsigned ah[2][4], al[2][4], bh[4][2], bl[4][2];
#pragma unroll
            for (int ma = 0; ma < 2; ma++) {
                int r0 = wm + ma * 16 + gid;
                ah[ma][0] = sAh[r0][kb + tig];
                ah[ma][1] = sAh[r0 + 8][kb + tig];
                ah[ma][2] = sAh[r0][kb + tig + 4];
                ah[ma][3] = sAh[r0 + 8][kb + tig + 4];
                al[ma][0] = sAl[r0][kb + tig];
                al[ma][1] = sAl[r0 + 8][kb + tig];
                al[ma][2] = sAl[r0][kb + tig + 4];
                al[ma][3] = sAl[r0 + 8][kb + tig + 4];
            }
#pragma unroll
            for (int na = 0; na < 4; na++) {
                int n0 = wn + na * 8 + gid;
                bh[na][0] = sBh[n0][kb + tig];
                bh[na][1] = sBh[n0][kb + tig + 4];
                bl[na][0] = sBl[n0][kb + tig];
                bl[na][1] = sBl[n0][kb + tig + 4];
            }
#pragma unroll
            for (int ma = 0; ma < 2; ma++)
#pragma unroll
                for (int na = 0; na < 4; na++) {
                    float* c = acc[ma][na];
                    mma_bf16(c[0], c[1], c[2], c[3],
                             ah[ma][0], ah[ma][1], ah[ma][2], ah[ma][3],
                             bh[na][0], bh[na][1]);
                    mma_bf16(c[0], c[1], c[2], c[3],
                             ah[ma][0], ah[ma][1], ah[ma][2], ah[ma][3],
                             bl[na][0], bl[na][1]);
                    mma_bf16(c[0], c[1], c[2], c[3],
                             al[ma][0], al[ma][1], al[ma][2], al[ma][3],
                             bh[na][0], bh[na][1]);
                }
        }
        __syncthreads();
    }

    // epilogue
#pragma unroll
    for (int ma = 0; ma < 2; ma++) {
        int gr0 = bm + wm + ma * 16 + gid;
        int gr1 = gr0 + 8;
#pragma unroll
        for (int na = 0; na < 4; na++) {
            int gc = bn + wn + na * 8 + tig * 2;
            float b0 = bias[gc], b1 = bias[gc + 1];
            float* c = acc[ma][na];
            if (gr0 < M) {
                float2 o = make_float2((c[0] + b0) * alpha, (c[1] + b1) * alpha);
                *(float2*)(C + (size_t)gr0 * D + gc) = o;
            }
            if (gr1 < M) {
                float2 o = make_float2((c[2] + b0) * alpha, (c[3] + b1) * alpha);
                *(float2*)(C + (size_t)gr1 * D + gc) = o;
            }
        }
    }
}

// ==================== CSR build ====================
__global__ void zero_kernel(int n)
{
    int i = blockIdx.x * blockDim.x + threadIdx.x;
    if (i < n) g_cnt[i] = 0;
}

__global__ void hist_kernel(const int* __restrict__ row, int E)
{
    int e = blockIdx.x * blockDim.x + threadIdx.x;
    if (e < E) atomicAdd(&g_cnt[row[e]], 1);
}

__global__ void scan_kernel(int n)
{
    __shared__ int warp_sums[32];
    __shared__ int carry;
    const int tid = threadIdx.x;
    const int lane = tid & 31;
    const int wid = tid >> 5;
    if (tid == 0) carry = 0;
    __syncthreads();
    for (int base = 0; base < n; base += 1024) {
        int i = base + tid;
        int v = (i < n) ? g_cnt[i] : 0;
        int x = v;
#pragma unroll
        for (int d = 1; d < 32; d <<= 1) {
            int y = __shfl_up_sync(0xffffffffu, x, d);
            if (lane >= d) x += y;
        }
        if (lane == 31) warp_sums[wid] = x;
        __syncthreads();
        if (wid == 0) {
            int sv = warp_sums[lane];
#pragma unroll
            for (int d = 1; d < 32; d <<= 1) {
                int y = __shfl_up_sync(0xffffffffu, sv, d);
                if (lane >= d) sv += y;
            }
            warp_sums[lane] = sv;
        }
        __syncthreads();
        int prefix = (wid > 0) ? warp_sums[wid - 1] : 0;
        int excl = x - v + prefix + carry;
        if (i < n) { g_ptr[i] = excl; g_fill[i] = excl; }
        int total = warp_sums[31];
        __syncthreads();
        if (tid == 0) carry = carry + total;
        __syncthreads();
    }
    if (tid == 0) g_ptr[n] = carry;
}

__global__ void scatter_kernel(const int* __restrict__ row,
                               const int* __restrict__ col, int E)
{
    int e = blockIdx.x * blockDim.x + threadIdx.x;
    if (e < E) {
        int p = atomicAdd(&g_fill[row[e]], 1);
        g_colbuf[p] = col[e];
    }
}

// ==================== per-node attention: 1 warp / node ====================
__global__ __launch_bounds__(256) void attn_kernel(int nnodes)
{
    const int lane = threadIdx.x & 31;
    const int node = blockIdx.x * 8 + (threadIdx.x >> 5);
    if (node >= nnodes) return;
    const int start = g_ptr[node];
    const int end = g_ptr[node + 1];

    const int b4 = (lane >> 4) & 1;
    const int b3 = (lane >> 3) & 1;
    const int b2 = (lane >> 2) & 1;
    const int myh = (b2 << 2) | (b3 << 1) | b4;
    const int hh = lane & 7;
    const int owner = ((hh & 1) << 4) | (((hh >> 1) & 1) << 3) | (((hh >> 2) & 1) << 2);

    const float4* qp = (const float4*)(g_q + (size_t)node * D + lane * 8);
    float4 q0 = qp[0], q1 = qp[1];

    float m_local = -1e30f;

    for (int base = start; base < end; base += 32) {
        int myj = 0;
        if (base + lane < end) myj = g_colbuf[base + lane];
        int cnt = min(32, end - base);
        for (int t = 0; t < cnt; t++) {
            int j = __shfl_sync(0xffffffffu, myj, t);
            const float4* kp = (const float4*)(g_k + (size_t)j * D + lane * 8);
            float4 k0 = kp[0], k1 = kp[1];
            float p0 = q0.x * k0.x, p1 = q0.y * k0.y, p2 = q0.z * k0.z, p3 = q0.w * k0.w;
            float p4 = q1.x * k1.x, p5 = q1.y * k1.y, p6 = q1.z * k1.z, p7 = q1.w * k1.w;
            float keep, send;
            keep = b4 ? p1 : p0; send = b4 ? p0 : p1;
            float tA0 = keep + __shfl_xor_sync(0xffffffffu, send, 16);
            keep = b4 ? p3 : p2; send = b4 ? p2 : p3;
            float tA1 = keep + __shfl_xor_sync(0xffffffffu, send, 16);
            keep = b4 ? p5 : p4; send = b4 ? p4 : p5;
            float tA2 = keep + __shfl_xor_sync(0xffffffffu, send, 16);
            keep = b4 ? p7 : p6; send = b4 ? p6 : p7;
            float tA3 = keep + __shfl_xor_sync(0xffffffffu, send, 16);
            keep = b3 ? tA1 : tA0; send = b3 ? tA0 : tA1;
            float tB0 = keep + __shfl_xor_sync(0xffffffffu, send, 8);
            keep = b3 ? tA3 : tA2; send = b3 ? tA2 : tA3;
            float tB1 = keep + __shfl_xor_sync(0xffffffffu, send, 8);
            keep = b2 ? tB1 : tB0; send = b2 ? tB0 : tB1;
            float s = keep + __shfl_xor_sync(0xffffffffu, send, 4);
            s += __shfl_xor_sync(0xffffffffu, s, 2);
            s += __shfl_xor_sync(0xffffffffu, s, 1);
            m_local = fmaxf(m_local, s);
            if ((lane & 3) == 0)
                g_s[(size_t)(base + t) * H + myh] = s;
        }
    }
    __threadfence_block();
    __syncwarp();

    float m2 = __shfl_sync(0xffffffffu, m_local, owner);

    float acc[8];
#pragma unroll
    for (int i = 0; i < 8; i++) acc[i] = 0.f;
    float z = 0.f;

    for (int base = start; base < end; base += 32) {
        int myj = 0;
        if (base + lane < end) myj = g_colbuf[base + lane];
        int cnt = min(32, end - base);
        for (int t = 0; t < cnt; t++) {
            int j = __shfl_sync(0xffffffffu, myj, t);
            float s = g_s[(size_t)(base + t) * H + hh];
            float w = __expf(s - m2);
            z += w;
            const float4* vp = (const float4*)(g_v + (size_t)j * D + lane * 8);
            float4 v0 = vp[0], v1 = vp[1];
            float vr[8] = {v0.x, v0.y, v0.z, v0.w, v1.x, v1.y, v1.z, v1.w};
#pragma unroll
            for (int i = 0; i < 8; i++) {
                float wi = __shfl_sync(0xffffffffu, w, i);
                acc[i] = fmaf(wi, vr[i], acc[i]);
            }
        }
    }
    float invz = (z > 0.f) ? (1.0f / z) : 0.f;
    float out[8];
#pragma unroll
    for (int i = 0; i < 8; i++)
        out[i] = acc[i] * __shfl_sync(0xffffffffu, invz, i);
    float4* op = (float4*)(g_attn + (size_t)node * D + lane * 8);
    op[0] = make_float4(out[0], out[1], out[2], out[3]);
    op[1] = make_float4(out[4], out[5], out[6], out[7]);
}

// ==================== launch ====================
extern "C" void kernel_launch(void* const* d_in, const int* in_sizes, int n_in,
                              void* d_out, int out_size)
{
    const float* x  = (const float*)d_in[0];
    const int*   row = (const int*)d_in[1];
    const int*   col = (const int*)d_in[2];
    const float* Wq = (const float*)d_in[3];
    const float* bq = (const float*)d_in[4];
    const float* Wk = (const float*)d_in[5];
    const float* bk = (const float*)d_in[6];
    const float* Wv = (const float*)d_in[7];
    const float* bv = (const float*)d_in[8];
    const float* Wo = (const float*)d_in[9];
    const float* bo = (const float*)d_in[10];
    float* out = (float*)d_out;

    const int N = in_sizes[0] / D;
    const int E = in_sizes[1];
    const float scaling = 0.17677669529663687f; // 32^-0.5

    // CSR build
    zero_kernel<<<(N + 255) / 256, 256>>>(N);
    hist_kernel<<<(E + 255) / 256, 256>>>(row, E);
    scan_kernel<<<1, 1024>>>(N);
    scatter_kernel<<<(E + 255) / 256, 256>>>(row, col, E);

    // convert weights (device-resolved tables) and x (reused by Q/K/V GEMMs)
    const int wgrid = (D * DP + 255) / 256;
    convert_w_kernel<<<wgrid, 256>>>(Wq, 0);
    convert_w_kernel<<<wgrid, 256>>>(Wk, 1);
    convert_w_kernel<<<wgrid, 256>>>(Wv, 2);
    convert_w_kernel<<<wgrid, 256>>>(Wo, 3);
    const int xgrid = (N * DP + 255) / 256;
    convert_x_kernel<<<xgrid, 256>>>(x, BUF_EXT, N);

    // projections (bf16x3 tensor cores); scaling folded into Q
    dim3 ggrid((N + 127) / 128, D / 64);
    gemm_bf16x3_kernel<<<ggrid, 256>>>(0, bq, nullptr, BUF_Q, N, scaling);
    gemm_bf16x3_kernel<<<ggrid, 256>>>(1, bk, nullptr, BUF_K, N, 1.f);
    gemm_bf16x3_kernel<<<ggrid, 256>>>(2, bv, nullptr, BUF_V, N, 1.f);

    // sparse attention (1 warp / node; g_s switches role to score buffer here)
    attn_kernel<<<(N + 7) / 8, 256>>>(N);

    // convert attention output (g_s switches back to split buffer), then out proj
    convert_x_kernel<<<xgrid, 256>>>(nullptr, BUF_ATTN, N);
    gemm_bf16x3_kernel<<<ggrid, 256>>>(3, bo, out, BUF_EXT, N, 1.f);
}

// round 10
// speedup vs baseline: 1.9023x; 1.4029x over previous
#include <cuda_runtime.h>
#include <cuda_bf16.h>
#include <cuda_fp16.h>
#include <math.h>
#include <stdint.h>

#define D 256
#define H 8
#define MAXN 50000
#define MAXE 1600000
#define DP (D / 2)                 // 128 k-pairs per row
#define XSP ((size_t)MAXN * DP)    // elements per x-split half

// -------- scratch (no allocs allowed -> device globals) --------
__device__ __align__(16) float g_q[(size_t)MAXN * D];      // fp32 Q
__device__ __align__(16) float g_attn[(size_t)MAXN * D];   // fp32 attn out
__device__ __align__(16) uint32_t g_kh[(size_t)MAXN * DP]; // K as half2 (25.6MB)
__device__ __align__(16) uint32_t g_vh[(size_t)MAXN * DP]; // V as half2 (25.6MB)
// g_s: phase-disjoint. GEMM phases: bf16-pair x-splits (hi [0,XSP), lo [XSP,2XSP)).
// attn_kernel: CSR-ordered fp32 scores [E][H].
__device__ __align__(16) float g_s[(size_t)MAXE * H];      // 51.2 MB
__device__ int g_cnt[MAXN];
__device__ int g_ptr[MAXN + 1];
__device__ int g_fill[MAXN];
__device__ int g_colbuf[MAXE];
__device__ __align__(16) uint32_t g_wth[4][D * DP];        // W^T [n][kpair] hi
__device__ __align__(16) uint32_t g_wtl[4][D * DP];        // W^T [n][kpair] lo

#define BUF_EXT  0
#define BUF_Q    1
#define BUF_ATTN 4

__device__ __forceinline__ float* buf_ptr(int id, float* ext)
{
    switch (id) {
        case BUF_Q:    return g_q;
        case BUF_ATTN: return g_attn;
        default:       return ext;
    }
}

// 2-way bf16 split of a float2 pair (hi = rn(x), lo = rn(x - hi))
__device__ __forceinline__ void split2(float2 a, uint32_t& s1, uint32_t& s2)
{
    __nv_bfloat162 h1 = __float22bfloat162_rn(a);
    float2 f1 = __bfloat1622float2(h1);
    __nv_bfloat162 h2 = __float22bfloat162_rn(make_float2(a.x - f1.x, a.y - f1.y));
    s1 = *(uint32_t*)&h1;
    s2 = *(uint32_t*)&h2;
}

__device__ __forceinline__ void mma_bf16(
    float* c,
    const uint32_t* a,
    uint32_t b0, uint32_t b1)
{
    asm volatile(
        "mma.sync.aligned.m16n8k16.row.col.f32.bf16.bf16.f32 "
        "{%0,%1,%2,%3}, {%4,%5,%6,%7}, {%8,%9}, {%0,%1,%2,%3};\n"
        : "+f"(c[0]), "+f"(c[1]), "+f"(c[2]), "+f"(c[3])
        : "r"(a[0]), "r"(a[1]), "r"(a[2]), "r"(a[3]), "r"(b0), "r"(b1));
}

__device__ __forceinline__ void ldsm4(uint32_t* r, uint32_t addr)
{
    asm volatile("ldmatrix.sync.aligned.m8n8.x4.shared.b16 {%0,%1,%2,%3}, [%4];"
                 : "=r"(r[0]), "=r"(r[1]), "=r"(r[2]), "=r"(r[3]) : "r"(addr));
}

__device__ __forceinline__ uint32_t smem_u32(const void* p)
{
    uint32_t a;
    asm("{ .reg .u64 t; cvta.to.shared.u64 t, %1; cvt.u32.u64 %0, t; }" : "=r"(a) : "l"(p));
    return a;
}

__device__ __forceinline__ void cp_async16(uint32_t dst, const void* src, int szbytes)
{
    asm volatile("cp.async.cg.shared.global [%0], [%1], 16, %2;"
                 :: "r"(dst), "l"(src), "r"(szbytes) : "memory");
}

// ==================== conversion passes ====================
__global__ __launch_bounds__(256) void convert_x_kernel(
    const float* __restrict__ X_ext, int X_id, int M)
{
    const float* X = buf_ptr(X_id, (float*)X_ext);
    uint32_t* xh = (uint32_t*)g_s;
    uint32_t* xl = (uint32_t*)g_s + XSP;
    int idx = blockIdx.x * blockDim.x + threadIdx.x;
    int total = M * DP;
    if (idx < total) {
        float2 v = *(const float2*)(X + (size_t)idx * 2);
        uint32_t h, l;
        split2(v, h, l);
        xh[idx] = h;
        xl[idx] = l;
    }
}

__global__ __launch_bounds__(256) void convert_w_kernel(
    const float* __restrict__ W, int widx)
{
    int slot = blockIdx.x * blockDim.x + threadIdx.x;
    if (slot < D * DP) {
        int n = slot & (D - 1);
        int kp = slot >> 8;
        float a0 = W[(size_t)(2 * kp) * D + n];
        float a1 = W[(size_t)(2 * kp + 1) * D + n];
        uint32_t h, l;
        split2(make_float2(a0, a1), h, l);
        g_wth[widx][(size_t)n * DP + kp] = h;
        g_wtl[widx][(size_t)n * DP + kp] = l;
    }
}

// ==================== bf16x3 mma GEMM, cp.async 2-stage + ldmatrix ====================
// C = alpha*(A@W + bias). BM=128 BN=64, k-iter = 16 kpairs (BK=32), 8 iters.
// SMEM row = 128B: [hi kp0-15 | lo kp0-15], 16B chunks XOR-swizzled by (row&7).
// hmode: 0 = fp32 C store; 1 = half2 -> g_kh; 2 = half2 -> g_vh.
__global__ __launch_bounds__(256) void gemm_bf16x3_kernel(
    int widx,
    const float* __restrict__ bias,
    float* __restrict__ C_ext, int C_id, int hmode,
    int M, float alpha)
{
    float* C = buf_ptr(C_id, C_ext);
    const uint32_t* __restrict__ WTh = g_wth[widx];
    const uint32_t* __restrict__ WTl = g_wtl[widx];
    const uint32_t* __restrict__ xh = (const uint32_t*)g_s;
    const uint32_t* __restrict__ xl = (const uint32_t*)g_s + XSP;

    __shared__ __align__(16) uint32_t sAbuf[2 * 128 * 32];  // 32 KB
    __shared__ __align__(16) uint32_t sBbuf[2 * 64 * 32];   // 16 KB

    const uint32_t baseA = smem_u32(sAbuf);
    const uint32_t baseB = smem_u32(sBbuf);

    const int tid = threadIdx.x;
    const int lane = tid & 31;
    const int warp = tid >> 5;
    const int lg = lane >> 3;
    const int li = lane & 7;
    const int gid = lane >> 2;
    const int tig = lane & 3;
    const int wm = (warp & 3) * 32;
    const int wn = (warp >> 2) * 32;
    const int bm = blockIdx.x * 128;
    const int bn = blockIdx.y * 64;

    // per-thread cp.async chunk assignments: 4 A-chunks + 2 B-chunks
    uint32_t adst[4]; size_t asrc[4]; int avalid[4], ahisel[4];
#pragma unroll
    for (int i = 0; i < 4; i++) {
        int c = tid + i * 256;          // 0..1023
        int r = c >> 3, ch = c & 7;
        adst[i] = r * 128u + ((ch ^ (r & 7)) * 16u);
        int gr = bm + r;
        avalid[i] = (gr < M) ? 16 : 0;
        asrc[i] = (size_t)((gr < M) ? gr : 0) * DP + (ch & 3) * 4;
        ahisel[i] = (ch < 4);
    }
    uint32_t bdst[2]; size_t bsrc[2]; int bhisel[2];
#pragma unroll
    for (int i = 0; i < 2; i++) {
        int c = tid + i * 256;          // 0..511
        int r = c >> 3, ch = c & 7;
        bdst[i] = r * 128u + ((ch ^ (r & 7)) * 16u);
        bsrc[i] = (size_t)(bn + r) * DP + (ch & 3) * 4;
        bhisel[i] = (ch < 4);
    }

#define COPY_TILE(st, k0p) do {                                               \
    _Pragma("unroll")                                                          \
    for (int i = 0; i < 4; i++) {                                              \
        const uint32_t* s = (ahisel[i] ? xh : xl) + asrc[i] + (k0p);           \
        cp_async16(baseA + (st) * 16384u + adst[i], s, avalid[i]);             \
    }                                                                          \
    _Pragma("unroll")                                                          \
    for (int i = 0; i < 2; i++) {                                              \
        const uint32_t* s = (bhisel[i] ? WTh : WTl) + bsrc[i] + (k0p);         \
        cp_async16(baseB + (st) * 8192u + bdst[i], s, 16);                     \
    }                                                                          \
    asm volatile("cp.async.commit_group;" ::: "memory");                       \
} while (0)

    float acc[2][4][4];
#pragma unroll
    for (int i = 0; i < 2; i++)
#pragma unroll
        for (int j = 0; j < 4; j++)
#pragma unroll
            for (int k = 0; k < 4; k++) acc[i][j][k] = 0.f;

    COPY_TILE(0, 0);

    for (int kt = 0; kt < 8; kt++) {
        if (kt < 7) {
            COPY_TILE((kt + 1) & 1, (kt + 1) * 16);
            asm volatile("cp.async.wait_group 1;" ::: "memory");
        } else {
            asm volatile("cp.async.wait_group 0;" ::: "memory");
        }
        __syncthreads();

        const uint32_t Ab = baseA + (kt & 1) * 16384u;
        const uint32_t Bb = baseB + (kt & 1) * 8192u;
#pragma unroll
        for (int ks = 0; ks < 2; ks++) {
            uint32_t ah[2][4], al[2][4], bh4[2][4], bl4[2][4];
#pragma unroll
            for (int ma = 0; ma < 2; ma++) {
                int row = wm + ma * 16 + (lg & 1) * 8 + li;
                int chh = ks * 2 + (lg >> 1);
                ldsm4(ah[ma], Ab + row * 128u + ((chh ^ (row & 7)) * 16u));
                ldsm4(al[ma], Ab + row * 128u + (((chh + 4) ^ (row & 7)) * 16u));
            }
#pragma unroll
            for (int p = 0; p < 2; p++) {
                int row = wn + p * 16 + (lg >> 1) * 8 + li;
                int chh = ks * 2 + (lg & 1);
                ldsm4(bh4[p], Bb + row * 128u + ((chh ^ (row & 7)) * 16u));
                ldsm4(bl4[p], Bb + row * 128u + (((chh + 4) ^ (row & 7)) * 16u));
            }
#pragma unroll
            for (int ma = 0; ma < 2; ma++)
#pragma unroll
                for (int p = 0; p < 2; p++) {
                    float* c0 = acc[ma][2 * p];
                    float* c1 = acc[ma][2 * p + 1];
                    mma_bf16(c0, ah[ma], bh4[p][0], bh4[p][1]);
                    mma_bf16(c0, ah[ma], bl4[p][0], bl4[p][1]);
                    mma_bf16(c0, al[ma], bh4[p][0], bh4[p][1]);
                    mma_bf16(c1, ah[ma], bh4[p][2], bh4[p][3]);
                    mma_bf16(c1, ah[ma], bl4[p][2], bl4[p][3]);
                    mma_bf16(c1, al[ma], bh4[p][2], bh4[p][3]);
                }
        }
        __syncthreads();
    }
#undef COPY_TILE

    // epilogue
#pragma unroll
    for (int ma = 0; ma < 2; ma++) {
        int gr0 = bm + wm + ma * 16 + gid;
        int gr1 = gr0 + 8;
#pragma unroll
        for (int na = 0; na < 4; na++) {
            int gc = bn + wn + na * 8 + tig * 2;
            float b0 = bias[gc], b1 = bias[gc + 1];
            float* c = acc[ma][na];
            if (hmode == 0) {
                if (gr0 < M) {
                    float2 o = make_float2((c[0] + b0) * alpha, (c[1] + b1) * alpha);
                    *(float2*)(C + (size_t)gr0 * D + gc) = o;
                }
                if (gr1 < M) {
                    float2 o = make_float2((c[2] + b0) * alpha, (c[3] + b1) * alpha);
                    *(float2*)(C + (size_t)gr1 * D + gc) = o;
                }
            } else {
                uint32_t* T = (hmode == 1) ? g_kh : g_vh;
                if (gr0 < M) {
                    __half2 hv = __floats2half2_rn((c[0] + b0) * alpha, (c[1] + b1) * alpha);
                    T[(size_t)gr0 * DP + (gc >> 1)] = *(uint32_t*)&hv;
                }
                if (gr1 < M) {
                    __half2 hv = __floats2half2_rn((c[2] + b0) * alpha, (c[3] + b1) * alpha);
                    T[(size_t)gr1 * DP + (gc >> 1)] = *(uint32_t*)&hv;
                }
            }
        }
    }
}

// ==================== CSR build ====================
__global__ void zero_kernel(int n)
{
    int i = blockIdx.x * blockDim.x + threadIdx.x;
    if (i < n) g_cnt[i] = 0;
}

__global__ void hist_kernel(const int* __restrict__ row, int E)
{
    int e = blockIdx.x * blockDim.x + threadIdx.x;
    if (e < E) atomicAdd(&g_cnt[row[e]], 1);
}

__global__ void scan_kernel(int n)
{
    __shared__ int warp_sums[32];
    __shared__ int carry;
    const int tid = threadIdx.x;
    const int lane = tid & 31;
    const int wid = tid >> 5;
    if (tid == 0) carry = 0;
    __syncthreads();
    for (int base = 0; base < n; base += 1024) {
        int i = base + tid;
        int v = (i < n) ? g_cnt[i] : 0;
        int x = v;
#pragma unroll
        for (int d = 1; d < 32; d <<= 1) {
            int y = __shfl_up_sync(0xffffffffu, x, d);
            if (lane >= d) x += y;
        }
        if (lane == 31) warp_sums[wid] = x;
        __syncthreads();
        if (wid == 0) {
            int sv = warp_sums[lane];
#pragma unroll
            for (int d = 1; d < 32; d <<= 1) {
                int y = __shfl_up_sync(0xffffffffu, sv, d);
                if (lane >= d) sv += y;
            }
            warp_sums[lane] = sv;
        }
        __syncthreads();
        int prefix = (wid > 0) ? warp_sums[wid - 1] : 0;
        int excl = x - v + prefix + carry;
        if (i < n) { g_ptr[i] = excl; g_fill[i] = excl; }
        int total = warp_sums[31];
        __syncthreads();
        if (tid == 0) carry = carry + total;
        __syncthreads();
    }
    if (tid == 0) g_ptr[n] = carry;
}

__global__ void scatter_kernel(const int* __restrict__ row,
                               const int* __restrict__ col, int E)
{
    int e = blockIdx.x * blockDim.x + threadIdx.x;
    if (e < E) {
        int p = atomicAdd(&g_fill[row[e]], 1);
        g_colbuf[p] = col[e];
    }
}

// ==================== per-node attention: 1 warp / node (fp16 K/V) ====================
__global__ __launch_bounds__(256) void attn_kernel(int nnodes)
{
    const int lane = threadIdx.x & 31;
    const int node = blockIdx.x * 8 + (threadIdx.x >> 5);
    if (node >= nnodes) return;
    const int start = g_ptr[node];
    const int end = g_ptr[node + 1];

    const int b4 = (lane >> 4) & 1;
    const int b3 = (lane >> 3) & 1;
    const int b2 = (lane >> 2) & 1;
    const int myh = (b2 << 2) | (b3 << 1) | b4;
    const int hh = lane & 7;
    const int owner = ((hh & 1) << 4) | (((hh >> 1) & 1) << 3) | (((hh >> 2) & 1) << 2);

    const float4* qp = (const float4*)(g_q + (size_t)node * D + lane * 8);
    float4 q0 = qp[0], q1 = qp[1];

    float m_local = -1e30f;

    // ---- phase 1: scores + per-head max ----
    for (int base = start; base < end; base += 32) {
        int myj = 0;
        if (base + lane < end) myj = g_colbuf[base + lane];
        int cnt = min(32, end - base);
        for (int t = 0; t < cnt; t++) {
            int j = __shfl_sync(0xffffffffu, myj, t);
            uint4 kv = ((const uint4*)(g_kh + (size_t)j * DP))[lane];
            float2 f0 = __half22float2(*(const __half2*)&kv.x);
            float2 f1 = __half22float2(*(const __half2*)&kv.y);
            float2 f2 = __half22float2(*(const __half2*)&kv.z);
            float2 f3 = __half22float2(*(const __half2*)&kv.w);
            float p0 = q0.x * f0.x, p1 = q0.y * f0.y, p2 = q0.z * f1.x, p3 = q0.w * f1.y;
            float p4 = q1.x * f2.x, p5 = q1.y * f2.y, p6 = q1.z * f3.x, p7 = q1.w * f3.y;
            float keep, send;
            keep = b4 ? p1 : p0; send = b4 ? p0 : p1;
            float tA0 = keep + __shfl_xor_sync(0xffffffffu, send, 16);
            keep = b4 ? p3 : p2; send = b4 ? p2 : p3;
            float tA1 = keep + __shfl_xor_sync(0xffffffffu, send, 16);
            keep = b4 ? p5 : p4; send = b4 ? p4 : p5;
            float tA2 = keep + __shfl_xor_sync(0xffffffffu, send, 16);
            keep = b4 ? p7 : p6; send = b4 ? p6 : p7;
            float tA3 = keep + __shfl_xor_sync(0xffffffffu, send, 16);
            keep = b3 ? tA1 : tA0; send = b3 ? tA0 : tA1;
            float tB0 = keep + __shfl_xor_sync(0xffffffffu, send, 8);
            keep = b3 ? tA3 : tA2; send = b3 ? tA2 : tA3;
            float tB1 = keep + __shfl_xor_sync(0xffffffffu, send, 8);
            keep = b2 ? tB1 : tB0; send = b2 ? tB0 : tB1;
            float s = keep + __shfl_xor_sync(0xffffffffu, send, 4);
            s += __shfl_xor_sync(0xffffffffu, s, 2);
            s += __shfl_xor_sync(0xffffffffu, s, 1);
            m_local = fmaxf(m_local, s);
            if ((lane & 3) == 0)
                g_s[(size_t)(base + t) * H + myh] = s;
        }
    }
    __threadfence_block();
    __syncwarp();

    float m2 = __shfl_sync(0xffffffffu, m_local, owner);

    // ---- phase 2: exp, z, weighted V accumulation ----
    float acc[8];
#pragma unroll
    for (int i = 0; i < 8; i++) acc[i] = 0.f;
    float z = 0.f;

    for (int base = start; base < end; base += 32) {
        int myj = 0;
        if (base + lane < end) myj = g_colbuf[base + lane];
        int cnt = min(32, end - base);
        for (int t = 0; t < cnt; t++) {
            int j = __shfl_sync(0xffffffffu, myj, t);
            float s = g_s[(size_t)(base + t) * H + hh];
            float w = __expf(s - m2);
            z += w;
            uint4 vv = ((const uint4*)(g_vh + (size_t)j * DP))[lane];
            float2 f0 = __half22float2(*(const __half2*)&vv.x);
            float2 f1 = __half22float2(*(const __half2*)&vv.y);
            float2 f2 = __half22float2(*(const __half2*)&vv.z);
            float2 f3 = __half22float2(*(const __half2*)&vv.w);
            float vr[8] = {f0.x, f0.y, f1.x, f1.y, f2.x, f2.y, f3.x, f3.y};
#pragma unroll
            for (int i = 0; i < 8; i++) {
                float wi = __shfl_sync(0xffffffffu, w, i);
                acc[i] = fmaf(wi, vr[i], acc[i]);
            }
        }
    }
    float invz = (z > 0.f) ? (1.0f / z) : 0.f;
    float out[8];
#pragma unroll
    for (int i = 0; i < 8; i++)
        out[i] = acc[i] * __shfl_sync(0xffffffffu, invz, i);
    float4* op = (float4*)(g_attn + (size_t)node * D + lane * 8);
    op[0] = make_float4(out[0], out[1], out[2], out[3]);
    op[1] = make_float4(out[4], out[5], out[6], out[7]);
}

// ==================== launch ====================
extern "C" void kernel_launch(void* const* d_in, const int* in_sizes, int n_in,
                              void* d_out, int out_size)
{
    const float* x  = (const float*)d_in[0];
    const int*   row = (const int*)d_in[1];
    const int*   col = (const int*)d_in[2];
    const float* Wq = (const float*)d_in[3];
    const float* bq = (const float*)d_in[4];
    const float* Wk = (const float*)d_in[5];
    const float* bk = (const float*)d_in[6];
    const float* Wv = (const float*)d_in[7];
    const float* bv = (const float*)d_in[8];
    const float* Wo = (const float*)d_in[9];
    const float* bo = (const float*)d_in[10];
    float* out = (float*)d_out;

    const int N = in_sizes[0] / D;
    const int E = in_sizes[1];
    const float scaling = 0.17677669529663687f; // 32^-0.5

    // CSR build
    zero_kernel<<<(N + 255) / 256, 256>>>(N);
    hist_kernel<<<(E + 255) / 256, 256>>>(row, E);
    scan_kernel<<<1, 1024>>>(N);
    scatter_kernel<<<(E + 255) / 256, 256>>>(row, col, E);

    // convert weights + x (x reused by Q/K/V GEMMs)
    const int wgrid = (D * DP + 255) / 256;
    convert_w_kernel<<<wgrid, 256>>>(Wq, 0);
    convert_w_kernel<<<wgrid, 256>>>(Wk, 1);
    convert_w_kernel<<<wgrid, 256>>>(Wv, 2);
    convert_w_kernel<<<wgrid, 256>>>(Wo, 3);
    const int xgrid = (N * DP + 255) / 256;
    convert_x_kernel<<<xgrid, 256>>>(x, BUF_EXT, N);

    // projections; Q -> fp32 (scaled), K/V -> fp16 tables
    dim3 ggrid((N + 127) / 128, D / 64);
    gemm_bf16x3_kernel<<<ggrid, 256>>>(0, bq, nullptr, BUF_Q, 0, N, scaling);
    gemm_bf16x3_kernel<<<ggrid, 256>>>(1, bk, nullptr, BUF_EXT, 1, N, 1.f);
    gemm_bf16x3_kernel<<<ggrid, 256>>>(2, bv, nullptr, BUF_EXT, 2, N, 1.f);

    // sparse attention (g_s switches role to score buffer here)
    attn_kernel<<<(N + 7) / 8, 256>>>(N);

    // convert attention output (g_s back to split role), then output projection
    convert_x_kernel<<<xgrid, 256>>>(nullptr, BUF_ATTN, N);
    gemm_bf16x3_kernel<<<ggrid, 256>>>(3, bo, out, BUF_EXT, 0, N, 1.f);
}

// round 12
// speedup vs baseline: 1.9625x; 1.0317x over previous
#include <cuda_runtime.h>
#include <cuda_bf16.h>
#include <cuda_fp16.h>
#include <math.h>
#include <stdint.h>

#define D 256
#define H 8
#define MAXN 50000
#define MAXE 1600000
#define DP (D / 2)                 // 128 k-pairs per row
#define XSP ((size_t)MAXN * DP)    // elements per split half

// -------- scratch (no allocs allowed -> device globals) --------
__device__ __align__(16) float g_q[(size_t)MAXN * D];      // fp32 Q (scaled)
__device__ __align__(16) uint32_t g_kh[(size_t)MAXN * DP]; // K as half2
__device__ __align__(16) uint32_t g_vh[(size_t)MAXN * DP]; // V as half2
// g_s: phase-disjoint. QKV-GEMM phase: bf16-pair x-splits (hi [0,XSP), lo [XSP,2XSP)).
// attn_kernel: CSR-ordered fp32 scores [E][H].
__device__ __align__(16) float g_s[(size_t)MAXE * H];      // 51.2 MB
__device__ __align__(16) uint32_t g_xs[2 * XSP];           // attn-out splits (51.2 MB)
__device__ int g_cnt[MAXN];
__device__ int g_ptr[MAXN + 1];
__device__ int g_fill[MAXN];
__device__ int g_colbuf[MAXE];
__device__ __align__(16) uint32_t g_wth[4][D * DP];        // W^T [n][kpair] hi
__device__ __align__(16) uint32_t g_wtl[4][D * DP];        // W^T [n][kpair] lo

// 2-way bf16 split of a float2 pair (hi = rn(x), lo = rn(x - hi))
__device__ __forceinline__ void split2(float2 a, uint32_t& s1, uint32_t& s2)
{
    __nv_bfloat162 h1 = __float22bfloat162_rn(a);
    float2 f1 = __bfloat1622float2(h1);
    __nv_bfloat162 h2 = __float22bfloat162_rn(make_float2(a.x - f1.x, a.y - f1.y));
    s1 = *(uint32_t*)&h1;
    s2 = *(uint32_t*)&h2;
}

__device__ __forceinline__ void mma_bf16(
    float* c, const uint32_t* a, uint32_t b0, uint32_t b1)
{
    asm volatile(
        "mma.sync.aligned.m16n8k16.row.col.f32.bf16.bf16.f32 "
        "{%0,%1,%2,%3}, {%4,%5,%6,%7}, {%8,%9}, {%0,%1,%2,%3};\n"
        : "+f"(c[0]), "+f"(c[1]), "+f"(c[2]), "+f"(c[3])
        : "r"(a[0]), "r"(a[1]), "r"(a[2]), "r"(a[3]), "r"(b0), "r"(b1));
}

__device__ __forceinline__ void ldsm4(uint32_t* r, uint32_t addr)
{
    asm volatile("ldmatrix.sync.aligned.m8n8.x4.shared.b16 {%0,%1,%2,%3}, [%4];"
                 : "=r"(r[0]), "=r"(r[1]), "=r"(r[2]), "=r"(r[3]) : "r"(addr));
}

__device__ __forceinline__ uint32_t smem_u32(const void* p)
{
    uint32_t a;
    asm("{ .reg .u64 t; cvta.to.shared.u64 t, %1; cvt.u32.u64 %0, t; }" : "=r"(a) : "l"(p));
    return a;
}

__device__ __forceinline__ void cp_async16(uint32_t dst, const void* src, int szbytes)
{
    asm volatile("cp.async.cg.shared.global [%0], [%1], 16, %2;"
                 :: "r"(dst), "l"(src), "r"(szbytes) : "memory");
}

// ==================== conversion passes ====================
__global__ __launch_bounds__(256) void convert_x_kernel(
    const float* __restrict__ X, int M)
{
    uint32_t* xh = (uint32_t*)g_s;
    uint32_t* xl = (uint32_t*)g_s + XSP;
    int idx = blockIdx.x * blockDim.x + threadIdx.x;
    if (idx < M * DP) {
        float2 v = *(const float2*)(X + (size_t)idx * 2);
        uint32_t h, l;
        split2(v, h, l);
        xh[idx] = h;
        xl[idx] = l;
    }
}

// all 4 weights in one launch: blockIdx.y = widx
__global__ __launch_bounds__(256) void convert_w_kernel(
    const float* __restrict__ Wq, const float* __restrict__ Wk,
    const float* __restrict__ Wv, const float* __restrict__ Wo)
{
    int widx = blockIdx.y;
    const float* W = (widx == 0) ? Wq : (widx == 1) ? Wk : (widx == 2) ? Wv : Wo;
    int slot = blockIdx.x * blockDim.x + threadIdx.x;
    if (slot < D * DP) {
        int n = slot & (D - 1);
        int kp = slot >> 8;
        float a0 = W[(size_t)(2 * kp) * D + n];
        float a1 = W[(size_t)(2 * kp + 1) * D + n];
        uint32_t h, l;
        split2(make_float2(a0, a1), h, l);
        g_wth[widx][(size_t)n * DP + kp] = h;
        g_wtl[widx][(size_t)n * DP + kp] = l;
    }
}

// ==================== bf16x3 mma GEMM, 3-stage cp.async + ldmatrix ====================
// mode 0: fused QKV (grid.y = 12; widx = y>>2, bn = (y&3)*64); A splits in g_s.
//   widx 0 -> fp32 g_q (alpha=scaling), widx 1 -> g_kh half2, widx 2 -> g_vh half2.
// mode 1: out-projection (grid.y = 4); A splits in g_xs; C = out_ext fp32.
// SMEM per stage: A 16 KB (128 rows x 128B), B 8 KB. 3 stages = 72 KB dynamic.
// Row = [hi kp0-15 | lo kp0-15], 16B chunks XOR-swizzled by (row&7).
#define GEMM_DSMEM (3 * (16384 + 8192))
__global__ __launch_bounds__(256) void gemm_fused_kernel(
    int mode,
    const float* __restrict__ bq, const float* __restrict__ bk,
    const float* __restrict__ bv, const float* __restrict__ bo,
    float* __restrict__ out_ext, int M, float scaling)
{
    extern __shared__ __align__(16) char dynsm[];
    const uint32_t sbase = smem_u32(dynsm);

    int widx, bn, hmode;
    const float* bias;
    float alpha;
    float* C = nullptr;
    const uint32_t *xh, *xl;
    if (mode == 0) {
        widx = blockIdx.y >> 2;
        bn = (blockIdx.y & 3) * 64;
        xh = (const uint32_t*)g_s;
        xl = (const uint32_t*)g_s + XSP;
        if (widx == 0)      { hmode = 0; C = g_q; bias = bq; alpha = scaling; }
        else if (widx == 1) { hmode = 1; bias = bk; alpha = 1.f; }
        else                { hmode = 2; bias = bv; alpha = 1.f; }
    } else {
        widx = 3;
        bn = blockIdx.y * 64;
        xh = g_xs;
        xl = g_xs + XSP;
        hmode = 0; C = out_ext; bias = bo; alpha = 1.f;
    }
    const uint32_t* __restrict__ WTh = g_wth[widx];
    const uint32_t* __restrict__ WTl = g_wtl[widx];

    const int tid = threadIdx.x;
    const int lane = tid & 31;
    const int warp = tid >> 5;
    const int lg = lane >> 3;
    const int li = lane & 7;
    const int gid = lane >> 2;
    const int tig = lane & 3;
    const int wm = (warp & 3) * 32;
    const int wn = (warp >> 2) * 32;
    const int bm = blockIdx.x * 128;

    // per-thread cp.async chunk assignments: 4 A-chunks + 2 B-chunks
    uint32_t adst[4]; size_t asrc[4]; int avalid[4], ahisel[4];
#pragma unroll
    for (int i = 0; i < 4; i++) {
        int c = tid + i * 256;          // 0..1023
        int r = c >> 3, ch = c & 7;
        adst[i] = r * 128u + ((ch ^ (r & 7)) * 16u);
        int gr = bm + r;
        avalid[i] = (gr < M) ? 16 : 0;
        asrc[i] = (size_t)((gr < M) ? gr : 0) * DP + (ch & 3) * 4;
        ahisel[i] = (ch < 4);
    }
    uint32_t bdst[2]; size_t bsrc[2]; int bhisel[2];
#pragma unroll
    for (int i = 0; i < 2; i++) {
        int c = tid + i * 256;          // 0..511
        int r = c >> 3, ch = c & 7;
        bdst[i] = r * 128u + ((ch ^ (r & 7)) * 16u);
        bsrc[i] = (size_t)(bn + r) * DP + (ch & 3) * 4;
        bhisel[i] = (ch < 4);
    }

#define STAGE_A(st) (sbase + (uint32_t)(st) * 16384u)
#define STAGE_B(st) (sbase + 49152u + (uint32_t)(st) * 8192u)
#define COPY_TILE(st, k0p) do {                                               \
    _Pragma("unroll")                                                          \
    for (int i = 0; i < 4; i++) {                                              \
        const uint32_t* s = (ahisel[i] ? xh : xl) + asrc[i] + (k0p);           \
        cp_async16(STAGE_A(st) + adst[i], s, avalid[i]);                       \
    }                                                                          \
    _Pragma("unroll")                                                          \
    for (int i = 0; i < 2; i++) {                                              \
        const uint32_t* s = (bhisel[i] ? WTh : WTl) + bsrc[i] + (k0p);         \
        cp_async16(STAGE_B(st) + bdst[i], s, 16);                              \
    }                                                                          \
    asm volatile("cp.async.commit_group;" ::: "memory");                       \
} while (0)

    float acc[2][4][4];
#pragma unroll
    for (int i = 0; i < 2; i++)
#pragma unroll
        for (int j = 0; j < 4; j++)
#pragma unroll
            for (int k = 0; k < 4; k++) acc[i][j][k] = 0.f;

    COPY_TILE(0, 0);
    COPY_TILE(1, 16);

    for (int kt = 0; kt < 8; kt++) {
        if (kt < 6)
            asm volatile("cp.async.wait_group 1;" ::: "memory");
        else
            asm volatile("cp.async.wait_group 0;" ::: "memory");
        __syncthreads();   // tile kt landed; all warps done with tile kt-1

        if (kt < 6)
            COPY_TILE((kt + 2) % 3, (kt + 2) * 16);

        const uint32_t Ab = STAGE_A(kt % 3);
        const uint32_t Bb = STAGE_B(kt % 3);
#pragma unroll
        for (int ks = 0; ks < 2; ks++) {
            uint32_t ah[2][4], al[2][4], bh4[2][4], bl4[2][4];
#pragma unroll
            for (int ma = 0; ma < 2; ma++) {
                int row = wm + ma * 16 + (lg & 1) * 8 + li;
                int chh = ks * 2 + (lg >> 1);
                ldsm4(ah[ma], Ab + row * 128u + ((chh ^ (row & 7)) * 16u));
                ldsm4(al[ma], Ab + row * 128u + (((chh + 4) ^ (row & 7)) * 16u));
            }
#pragma unroll
            for (int p = 0; p < 2; p++) {
                int row = wn + p * 16 + (lg >> 1) * 8 + li;
                int chh = ks * 2 + (lg & 1);
                ldsm4(bh4[p], Bb + row * 128u + ((chh ^ (row & 7)) * 16u));
                ldsm4(bl4[p], Bb + row * 128u + (((chh + 4) ^ (row & 7)) * 16u));
            }
#pragma unroll
            for (int ma = 0; ma < 2; ma++)
#pragma unroll
                for (int p = 0; p < 2; p++) {
                    float* c0 = acc[ma][2 * p];
                    float* c1 = acc[ma][2 * p + 1];
                    mma_bf16(c0, ah[ma], bh4[p][0], bh4[p][1]);
                    mma_bf16(c0, ah[ma], bl4[p][0], bl4[p][1]);
                    mma_bf16(c0, al[ma], bh4[p][0], bh4[p][1]);
                    mma_bf16(c1, ah[ma], bh4[p][2], bh4[p][3]);
                    mma_bf16(c1, ah[ma], bl4[p][2], bl4[p][3]);
                    mma_bf16(c1, al[ma], bh4[p][2], bh4[p][3]);
                }
        }
    }
#undef COPY_TILE
#undef STAGE_A
#undef STAGE_B

    // epilogue
#pragma unroll
    for (int ma = 0; ma < 2; ma++) {
        int gr0 = bm + wm + ma * 16 + gid;
        int gr1 = gr0 + 8;
#pragma unroll
        for (int na = 0; na < 4; na++) {
            int gc = bn + wn + na * 8 + tig * 2;
            float b0 = bias[gc], b1 = bias[gc + 1];
            float* c = acc[ma][na];
            if (hmode == 0) {
                if (gr0 < M) {
                    float2 o = make_float2((c[0] + b0) * alpha, (c[1] + b1) * alpha);
                    *(float2*)(C + (size_t)gr0 * D + gc) = o;
                }
                if (gr1 < M) {
                    float2 o = make_float2((c[2] + b0) * alpha, (c[3] + b1) * alpha);
                    *(float2*)(C + (size_t)gr1 * D + gc) = o;
                }
            } else {
                uint32_t* T = (hmode == 1) ? g_kh : g_vh;
                if (gr0 < M) {
                    __half2 hv = __floats2half2_rn((c[0] + b0) * alpha, (c[1] + b1) * alpha);
                    T[(size_t)gr0 * DP + (gc >> 1)] = *(uint32_t*)&hv;
                }
                if (gr1 < M) {
                    __half2 hv = __floats2half2_rn((c[2] + b0) * alpha, (c[3] + b1) * alpha);
                    T[(size_t)gr1 * DP + (gc >> 1)] = *(uint32_t*)&hv;
                }
            }
        }
    }
}

// ==================== CSR build ====================
__global__ void zero_kernel(int n)
{
    int i = blockIdx.x * blockDim.x + threadIdx.x;
    if (i < n) g_cnt[i] = 0;
}

__global__ void hist_kernel(const int* __restrict__ row, int E)
{
    int e = blockIdx.x * blockDim.x + threadIdx.x;
    if (e < E) atomicAdd(&g_cnt[row[e]], 1);
}

__global__ void scan_kernel(int n)
{
    __shared__ int warp_sums[32];
    __shared__ int carry;
    const int tid = threadIdx.x;
    const int lane = tid & 31;
    const int wid = tid >> 5;
    if (tid == 0) carry = 0;
    __syncthreads();
    for (int base = 0; base < n; base += 1024) {
        int i = base + tid;
        int v = (i < n) ? g_cnt[i] : 0;
        int x = v;
#pragma unroll
        for (int d = 1; d < 32; d <<= 1) {
            int y = __shfl_up_sync(0xffffffffu, x, d);
            if (lane >= d) x += y;
        }
        if (lane == 31) warp_sums[wid] = x;
        __syncthreads();
        if (wid == 0) {
            int sv = warp_sums[lane];
#pragma unroll
            for (int d = 1; d < 32; d <<= 1) {
                int y = __shfl_up_sync(0xffffffffu, sv, d);
                if (lane >= d) sv += y;
            }
            warp_sums[lane] = sv;
        }
        __syncthreads();
        int prefix = (wid > 0) ? warp_sums[wid - 1] : 0;
        int excl = x - v + prefix + carry;
        if (i < n) { g_ptr[i] = excl; g_fill[i] = excl; }
        int total = warp_sums[31];
        __syncthreads();
        if (tid == 0) carry = carry + total;
        __syncthreads();
    }
    if (tid == 0) g_ptr[n] = carry;
}

__global__ void scatter_kernel(const int* __restrict__ row,
                               const int* __restrict__ col, int E)
{
    int e = blockIdx.x * blockDim.x + threadIdx.x;
    if (e < E) {
        int p = atomicAdd(&g_fill[row[e]], 1);
        g_colbuf[p] = col[e];
    }
}

// ==================== per-node attention: 1 warp / node (fp16 K/V) ====================
// Epilogue writes bf16 splits for the output projection directly into g_xs.
__global__ __launch_bounds__(256) void attn_kernel(int nnodes)
{
    const int lane = threadIdx.x & 31;
    const int node = blockIdx.x * 8 + (threadIdx.x >> 5);
    if (node >= nnodes) return;
    const int start = g_ptr[node];
    const int end = g_ptr[node + 1];

    const int b4 = (lane >> 4) & 1;
    const int b3 = (lane >> 3) & 1;
    const int b2 = (lane >> 2) & 1;
    const int myh = (b2 << 2) | (b3 << 1) | b4;
    const int hh = lane & 7;
    const int owner = ((hh & 1) << 4) | (((hh >> 1) & 1) << 3) | (((hh >> 2) & 1) << 2);

    const float4* qp = (const float4*)(g_q + (size_t)node * D + lane * 8);
    float4 q0 = qp[0], q1 = qp[1];

    float m_local = -1e30f;

    // ---- phase 1: scores + per-head max ----
    for (int base = start; base < end; base += 32) {
        int myj = 0;
        if (base + lane < end) myj = g_colbuf[base + lane];
        int cnt = min(32, end - base);
        for (int t = 0; t < cnt; t++) {
            int j = __shfl_sync(0xffffffffu, myj, t);
            uint4 kv = ((const uint4*)(g_kh + (size_t)j * DP))[lane];
            float2 f0 = __half22float2(*(const __half2*)&kv.x);
            float2 f1 = __half22float2(*(const __half2*)&kv.y);
            float2 f2 = __half22float2(*(const __half2*)&kv.z);
            float2 f3 = __half22float2(*(const __half2*)&kv.w);
            float p0 = q0.x * f0.x, p1 = q0.y * f0.y, p2 = q0.z * f1.x, p3 = q0.w * f1.y;
            float p4 = q1.x * f2.x, p5 = q1.y * f2.y, p6 = q1.z * f3.x, p7 = q1.w * f3.y;
            float keep, send;
            keep = b4 ? p1 : p0; send = b4 ? p0 : p1;
            float tA0 = keep + __shfl_xor_sync(0xffffffffu, send, 16);
            keep = b4 ? p3 : p2; send = b4 ? p2 : p3;
            float tA1 = keep + __shfl_xor_sync(0xffffffffu, send, 16);
            keep = b4 ? p5 : p4; send = b4 ? p4 : p5;
            float tA2 = keep + __shfl_xor_sync(0xffffffffu, send, 16);
            keep = b4 ? p7 : p6; send = b4 ? p6 : p7;
            float tA3 = keep + __shfl_xor_sync(0xffffffffu, send, 16);
            keep = b3 ? tA1 : tA0; send = b3 ? tA0 : tA1;
            float tB0 = keep + __shfl_xor_sync(0xffffffffu, send, 8);
            keep = b3 ? tA3 : tA2; send = b3 ? tA2 : tA3;
            float tB1 = keep + __shfl_xor_sync(0xffffffffu, send, 8);
            keep = b2 ? tB1 : tB0; send = b2 ? tB0 : tB1;
            float s = keep + __shfl_xor_sync(0xffffffffu, send, 4);
            s += __shfl_xor_sync(0xffffffffu, s, 2);
            s += __shfl_xor_sync(0xffffffffu, s, 1);
            m_local = fmaxf(m_local, s);
            if ((lane & 3) == 0)
                g_s[(size_t)(base + t) * H + myh] = s;
        }
    }
    __threadfence_block();
    __syncwarp();

    float m2 = __shfl_sync(0xffffffffu, m_local, owner);

    // ---- phase 2: exp, z, weighted V accumulation ----
    float acc[8];
#pragma unroll
    for (int i = 0; i < 8; i++) acc[i] = 0.f;
    float z = 0.f;

    for (int base = start; base < end; base += 32) {
        int myj = 0;
        if (base + lane < end) myj = g_colbuf[base + lane];
        int cnt = min(32, end - base);
        for (int t = 0; t < cnt; t++) {
            int j = __shfl_sync(0xffffffffu, myj, t);
            float s = g_s[(size_t)(base + t) * H + hh];
            float w = __expf(s - m2);
            z += w;
            uint4 vv = ((const uint4*)(g_vh + (size_t)j * DP))[lane];
            float2 f0 = __half22float2(*(const __half2*)&vv.x);
            float2 f1 = __half22float2(*(const __half2*)&vv.y);
            float2 f2 = __half22float2(*(const __half2*)&vv.z);
            float2 f3 = __half22float2(*(const __half2*)&vv.w);
            float vr[8] = {f0.x, f0.y, f1.x, f1.y, f2.x, f2.y, f3.x, f3.y};
#pragma unroll
            for (int i = 0; i < 8; i++) {
                float wi = __shfl_sync(0xffffffffu, w, i);
                acc[i] = fmaf(wi, vr[i], acc[i]);
            }
        }
    }
    float invz = (z > 0.f) ? (1.0f / z) : 0.f;
    float out[8];
#pragma unroll
    for (int i = 0; i < 8; i++)
        out[i] = acc[i] * __shfl_sync(0xffffffffu, invz, i);

    // split to bf16 pairs for the output projection
    uint32_t hs[4], ls[4];
#pragma unroll
    for (int i = 0; i < 4; i++)
        split2(make_float2(out[2 * i], out[2 * i + 1]), hs[i], ls[i]);
    uint32_t* xo = g_xs + (size_t)node * DP + lane * 4;
    *(uint4*)xo = make_uint4(hs[0], hs[1], hs[2], hs[3]);
    *(uint4*)(xo + XSP) = make_uint4(ls[0], ls[1], ls[2], ls[3]);
}

// ==================== launch ====================
extern "C" void kernel_launch(void* const* d_in, const int* in_sizes, int n_in,
                              void* d_out, int out_size)
{
    const float* x  = (const float*)d_in[0];
    const int*   row = (const int*)d_in[1];
    const int*   col = (const int*)d_in[2];
    const float* Wq = (const float*)d_in[3];
    const float* bq = (const float*)d_in[4];
    const float* Wk = (const float*)d_in[5];
    const float* bk = (const float*)d_in[6];
    const float* Wv = (const float*)d_in[7];
    const float* bv = (const float*)d_in[8];
    const float* Wo = (const float*)d_in[9];
    const float* bo = (const float*)d_in[10];
    float* out = (float*)d_out;

    const int N = in_sizes[0] / D;
    const int E = in_sizes[1];
    const float scaling = 0.17677669529663687f; // 32^-0.5

    cudaFuncSetAttribute(gemm_fused_kernel,
                         cudaFuncAttributeMaxDynamicSharedMemorySize, GEMM_DSMEM);

    // CSR build
    zero_kernel<<<(N + 255) / 256, 256>>>(N);
    hist_kernel<<<(E + 255) / 256, 256>>>(row, E);
    scan_kernel<<<1, 1024>>>(N);
    scatter_kernel<<<(E + 255) / 256, 256>>>(row, col, E);

    // conversions: 4 weights fused; x splits into g_s
    dim3 wgrid((D * DP + 255) / 256, 4);
    convert_w_kernel<<<wgrid, 256>>>(Wq, Wk, Wv, Wo);
    convert_x_kernel<<<(N * DP + 255) / 256, 256>>>(x, N);

    // fused QKV projection (12 n-blocks: Q fp32, K/V fp16 tables)
    dim3 qkvgrid((N + 127) / 128, 12);
    gemm_fused_kernel<<<qkvgrid, 256, GEMM_DSMEM>>>(0, bq, bk, bv, bo, nullptr, N, scaling);

    // sparse attention (g_s becomes score buffer; epilogue writes g_xs splits)
    attn_kernel<<<(N + 7) / 8, 256>>>(N);

    // output projection from g_xs splits
    dim3 ogrid((N + 127) / 128, 4);
    gemm_fused_kernel<<<ogrid, 256, GEMM_DSMEM>>>(1, bq, bk, bv, bo, out, N, scaling);
}

// round 15
// speedup vs baseline: 2.3818x; 1.2136x over previous
#include <cuda_runtime.h>
#include <cuda_bf16.h>
#include <cuda_fp16.h>
#include <math.h>
#include <stdint.h>

#define D 256
#define H 8
#define MAXN 50000
#define MAXE 1600000
#define DP (D / 2)                 // 128 k-pairs per row
#define XSP ((size_t)MAXN * DP)    // elements per split half

// -------- scratch (no allocs allowed -> device globals) --------
__device__ __align__(16) float g_q[(size_t)MAXN * D];      // fp32 Q (scaled)
__device__ __align__(16) uint32_t g_kh[(size_t)MAXN * DP]; // K as half2
__device__ __align__(16) uint32_t g_vh[(size_t)MAXN * DP]; // V as half2
__device__ __align__(16) uint32_t g_s[2 * XSP];            // x fp16 splits (h|l planes)
__device__ __align__(16) uint32_t g_xs[2 * XSP];           // attn-out bf16 splits
__device__ int g_cnt[MAXN];
__device__ int g_ptr[MAXN + 1];
__device__ int g_fill[MAXN];
__device__ int g_colbuf[MAXE];
__device__ __align__(16) uint32_t g_wf16[3][D * DP];       // Wq/Wk/Wv^T [n][kpair] fp16
__device__ __align__(16) uint32_t g_woh[D * DP];           // Wo^T bf16 hi
__device__ __align__(16) uint32_t g_wol[D * DP];           // Wo^T bf16 lo

// owner lane of head i in the butterfly layout (b2=i>>2, b3=(i>>1)&1, b4=i&1)
#define OWNER(i) ((((i) & 1) << 4) | ((((i) >> 1) & 1) << 3) | ((((i) >> 2) & 1) << 2))

// 2-way bf16 split
__device__ __forceinline__ void split2_bf16(float2 a, uint32_t& s1, uint32_t& s2)
{
    __nv_bfloat162 h1 = __float22bfloat162_rn(a);
    float2 f1 = __bfloat1622float2(h1);
    __nv_bfloat162 h2 = __float22bfloat162_rn(make_float2(a.x - f1.x, a.y - f1.y));
    s1 = *(uint32_t*)&h1;
    s2 = *(uint32_t*)&h2;
}

// 2-way fp16 split
__device__ __forceinline__ void split2_f16(float2 a, uint32_t& s1, uint32_t& s2)
{
    __half2 h1 = __floats2half2_rn(a.x, a.y);
    float2 f1 = __half22float2(h1);
    __half2 h2 = __floats2half2_rn(a.x - f1.x, a.y - f1.y);
    s1 = *(uint32_t*)&h1;
    s2 = *(uint32_t*)&h2;
}

__device__ __forceinline__ void mma_bf16(
    float* c, const uint32_t* a, uint32_t b0, uint32_t b1)
{
    asm volatile(
        "mma.sync.aligned.m16n8k16.row.col.f32.bf16.bf16.f32 "
        "{%0,%1,%2,%3}, {%4,%5,%6,%7}, {%8,%9}, {%0,%1,%2,%3};\n"
        : "+f"(c[0]), "+f"(c[1]), "+f"(c[2]), "+f"(c[3])
        : "r"(a[0]), "r"(a[1]), "r"(a[2]), "r"(a[3]), "r"(b0), "r"(b1));
}

__device__ __forceinline__ void mma_f16(
    float* c, const uint32_t* a, uint32_t b0, uint32_t b1)
{
    asm volatile(
        "mma.sync.aligned.m16n8k16.row.col.f32.f16.f16.f32 "
        "{%0,%1,%2,%3}, {%4,%5,%6,%7}, {%8,%9}, {%0,%1,%2,%3};\n"
        : "+f"(c[0]), "+f"(c[1]), "+f"(c[2]), "+f"(c[3])
        : "r"(a[0]), "r"(a[1]), "r"(a[2]), "r"(a[3]), "r"(b0), "r"(b1));
}

__device__ __forceinline__ void ldsm4(uint32_t* r, uint32_t addr)
{
    asm volatile("ldmatrix.sync.aligned.m8n8.x4.shared.b16 {%0,%1,%2,%3}, [%4];"
                 : "=r"(r[0]), "=r"(r[1]), "=r"(r[2]), "=r"(r[3]) : "r"(addr));
}

__device__ __forceinline__ uint32_t smem_u32(const void* p)
{
    uint32_t a;
    asm("{ .reg .u64 t; cvta.to.shared.u64 t, %1; cvt.u32.u64 %0, t; }" : "=r"(a) : "l"(p));
    return a;
}

__device__ __forceinline__ void cp_async16(uint32_t dst, const void* src, int szbytes)
{
    asm volatile("cp.async.cg.shared.global [%0], [%1], 16, %2;"
                 :: "r"(dst), "l"(src), "r"(szbytes) : "memory");
}

// ==================== conversion passes ====================
// x -> fp16 split planes in g_s
__global__ __launch_bounds__(256) void convert_x_kernel(
    const float* __restrict__ X, int M)
{
    int idx = blockIdx.x * blockDim.x + threadIdx.x;
    if (idx < M * DP) {
        float2 v = *(const float2*)(X + (size_t)idx * 2);
        uint32_t h, l;
        split2_f16(v, h, l);
        g_s[idx] = h;
        g_s[XSP + idx] = l;
    }
}

// blockIdx.y = widx: 0-2 -> fp16 single plane; 3 -> bf16 hi/lo planes (Wo)
__global__ __launch_bounds__(256) void convert_w_kernel(
    const float* __restrict__ Wq, const float* __restrict__ Wk,
    const float* __restrict__ Wv, const float* __restrict__ Wo)
{
    int widx = blockIdx.y;
    const float* W = (widx == 0) ? Wq : (widx == 1) ? Wk : (widx == 2) ? Wv : Wo;
    int slot = blockIdx.x * blockDim.x + threadIdx.x;
    if (slot < D * DP) {
        int n = slot & (D - 1);
        int kp = slot >> 8;
        float a0 = W[(size_t)(2 * kp) * D + n];
        float a1 = W[(size_t)(2 * kp + 1) * D + n];
        if (widx < 3) {
            __half2 hv = __floats2half2_rn(a0, a1);
            g_wf16[widx][(size_t)n * DP + kp] = *(uint32_t*)&hv;
        } else {
            uint32_t h, l;
            split2_bf16(make_float2(a0, a1), h, l);
            g_woh[(size_t)n * DP + kp] = h;
            g_wol[(size_t)n * DP + kp] = l;
        }
    }
}

// ==================== QKV GEMM: fp16 x2-product, 3-stage cp.async ====================
// grid.y = 12: widx = y>>2 (0=Q,1=K,2=V), bn = (y&3)*64.
// A: fp16 split planes in g_s (h exact + l) -> (xh+xl)*Wh = x*Wh exactly.
// B: single fp16 plane; smem row stride 80 B (20r mod 32 -> conflict-free ldsm, no swizzle).
// SMEM/stage: A 16 KB, B 5 KB; 3 stages = 64512 B dynamic.
#define QKV_DSMEM (3 * (16384 + 5120))
__global__ __launch_bounds__(256) void gemm_qkv_kernel(
    const float* __restrict__ bq, const float* __restrict__ bk,
    const float* __restrict__ bv, int M, float scaling)
{
    extern __shared__ __align__(16) char dynsm[];
    const uint32_t sbase = smem_u32(dynsm);

    const int widx = blockIdx.y >> 2;
    const int bn = (blockIdx.y & 3) * 64;
    const float* bias = (widx == 0) ? bq : (widx == 1) ? bk : bv;
    const float alpha = (widx == 0) ? scaling : 1.f;
    const uint32_t* __restrict__ WT = g_wf16[widx];
    const uint32_t* __restrict__ xh = g_s;
    const uint32_t* __restrict__ xl = g_s + XSP;

    const int tid = threadIdx.x;
    const int lane = tid & 31;
    const int warp = tid >> 5;
    const int lg = lane >> 3;
    const int li = lane & 7;
    const int gid = lane >> 2;
    const int tig = lane & 3;
    const int wm = (warp & 3) * 32;
    const int wn = (warp >> 2) * 32;
    const int bm = blockIdx.x * 128;

    // A: 4 chunks/thread (128 rows x 8 chunks of 16B: hi 0-3 | lo 4-7, XOR swizzle)
    uint32_t adst[4]; size_t asrc[4]; int avalid[4], ahisel[4];
#pragma unroll
    for (int i = 0; i < 4; i++) {
        int c = tid + i * 256;
        int r = c >> 3, ch = c & 7;
        adst[i] = r * 128u + ((ch ^ (r & 7)) * 16u);
        int gr = bm + r;
        avalid[i] = (gr < M) ? 16 : 0;
        asrc[i] = (size_t)((gr < M) ? gr : 0) * DP + (ch & 3) * 4;
        ahisel[i] = (ch < 4);
    }
    // B: 1 chunk/thread (64 rows x 4 chunks of 16B, stride 80)
    const int br = tid >> 2;
    const int bch = tid & 3;
    const uint32_t bdst = br * 80u + bch * 16u;
    const size_t bsrc = (size_t)(bn + br) * DP + bch * 4;

#define STAGE_A(st) (sbase + (uint32_t)(st) * 16384u)
#define STAGE_B(st) (sbase + 49152u + (uint32_t)(st) * 5120u)
#define COPY_TILE(st, k0p) do {                                               \
    _Pragma("unroll")                                                          \
    for (int i = 0; i < 4; i++) {                                              \
        const uint32_t* s = (ahisel[i] ? xh : xl) + asrc[i] + (k0p);           \
        cp_async16(STAGE_A(st) + adst[i], s, avalid[i]);                       \
    }                                                                          \
    cp_async16(STAGE_B(st) + bdst, WT + bsrc + (k0p), 16);                     \
    asm volatile("cp.async.commit_group;" ::: "memory");                       \
} while (0)

    float acc[2][4][4];
#pragma unroll
    for (int i = 0; i < 2; i++)
#pragma unroll
        for (int j = 0; j < 4; j++)
#pragma unroll
            for (int k = 0; k < 4; k++) acc[i][j][k] = 0.f;

    COPY_TILE(0, 0);
    COPY_TILE(1, 16);

    for (int kt = 0; kt < 8; kt++) {
        if (kt < 6)
            asm volatile("cp.async.wait_group 1;" ::: "memory");
        else
            asm volatile("cp.async.wait_group 0;" ::: "memory");
        __syncthreads();

        if (kt < 6)
            COPY_TILE((kt + 2) % 3, (kt + 2) * 16);

        const uint32_t Ab = STAGE_A(kt % 3);
        const uint32_t Bb = STAGE_B(kt % 3);
#pragma unroll
        for (int ks = 0; ks < 2; ks++) {
            uint32_t ah[2][4], al[2][4], bb[2][4];
#pragma unroll
            for (int ma = 0; ma < 2; ma++) {
                int row = wm + ma * 16 + (lg & 1) * 8 + li;
                int chh = ks * 2 + (lg >> 1);
                ldsm4(ah[ma], Ab + row * 128u + ((chh ^ (row & 7)) * 16u));
                ldsm4(al[ma], Ab + row * 128u + (((chh + 4) ^ (row & 7)) * 16u));
            }
#pragma unroll
            for (int p = 0; p < 2; p++) {
                int row = wn + p * 16 + (lg >> 1) * 8 + li;
                int chh = ks * 2 + (lg & 1);
                ldsm4(bb[p], Bb + row * 80u + chh * 16u);
            }
#pragma unroll
            for (int ma = 0; ma < 2; ma++)
#pragma unroll
                for (int p = 0; p < 2; p++) {
                    float* c0 = acc[ma][2 * p];
                    float* c1 = acc[ma][2 * p + 1];
                    mma_f16(c0, ah[ma], bb[p][0], bb[p][1]);
                    mma_f16(c0, al[ma], bb[p][0], bb[p][1]);
                    mma_f16(c1, ah[ma], bb[p][2], bb[p][3]);
                    mma_f16(c1, al[ma], bb[p][2], bb[p][3]);
                }
        }
    }
#undef COPY_TILE
#undef STAGE_A
#undef STAGE_B

    // epilogue: widx0 -> fp32 Q (scaled); widx1/2 -> fp16 tables
#pragma unroll
    for (int ma = 0; ma < 2; ma++) {
        int gr0 = bm + wm + ma * 16 + gid;
        int gr1 = gr0 + 8;
#pragma unroll
        for (int na = 0; na < 4; na++) {
            int gc = bn + wn + na * 8 + tig * 2;
            float b0 = bias[gc], b1 = bias[gc + 1];
            float* c = acc[ma][na];
            if (widx == 0) {
                if (gr0 < M)
                    *(float2*)(g_q + (size_t)gr0 * D + gc) =
                        make_float2((c[0] + b0) * alpha, (c[1] + b1) * alpha);
                if (gr1 < M)
                    *(float2*)(g_q + (size_t)gr1 * D + gc) =
                        make_float2((c[2] + b0) * alpha, (c[3] + b1) * alpha);
            } else {
                uint32_t* T = (widx == 1) ? g_kh : g_vh;
                if (gr0 < M) {
                    __half2 hv = __floats2half2_rn(c[0] + b0, c[1] + b1);
                    T[(size_t)gr0 * DP + (gc >> 1)] = *(uint32_t*)&hv;
                }
                if (gr1 < M) {
                    __half2 hv = __floats2half2_rn(c[2] + b0, c[3] + b1);
                    T[(size_t)gr1 * DP + (gc >> 1)] = *(uint32_t*)&hv;
                }
            }
        }
    }
}

// ==================== O GEMM: bf16 x3-product (unchanged numerics) ====================
#define O_DSMEM (3 * (16384 + 8192))
__global__ __launch_bounds__(256) void gemm_o_kernel(
    const float* __restrict__ bo, float* __restrict__ out, int M)
{
    extern __shared__ __align__(16) char dynsm[];
    const uint32_t sbase = smem_u32(dynsm);
    const int bn = blockIdx.y * 64;
    const uint32_t* __restrict__ xh = g_xs;
    const uint32_t* __restrict__ xl = g_xs + XSP;

    const int tid = threadIdx.x;
    const int lane = tid & 31;
    const int warp = tid >> 5;
    const int lg = lane >> 3;
    const int li = lane & 7;
    const int gid = lane >> 2;
    const int tig = lane & 3;
    const int wm = (warp & 3) * 32;
    const int wn = (warp >> 2) * 32;
    const int bm = blockIdx.x * 128;

    uint32_t adst[4]; size_t asrc[4]; int avalid[4], ahisel[4];
#pragma unroll
    for (int i = 0; i < 4; i++) {
        int c = tid + i * 256;
        int r = c >> 3, ch = c & 7;
        adst[i] = r * 128u + ((ch ^ (r & 7)) * 16u);
        int gr = bm + r;
        avalid[i] = (gr < M) ? 16 : 0;
        asrc[i] = (size_t)((gr < M) ? gr : 0) * DP + (ch & 3) * 4;
        ahisel[i] = (ch < 4);
    }
    uint32_t bdst[2]; size_t bsrc[2]; int bhisel[2];
#pragma unroll
    for (int i = 0; i < 2; i++) {
        int c = tid + i * 256;
        int r = c >> 3, ch = c & 7;
        bdst[i] = r * 128u + ((ch ^ (r & 7)) * 16u);
        bsrc[i] = (size_t)(bn + r) * DP + (ch & 3) * 4;
        bhisel[i] = (ch < 4);
    }

#define STAGE_A(st) (sbase + (uint32_t)(st) * 16384u)
#define STAGE_B(st) (sbase + 49152u + (uint32_t)(st) * 8192u)
#define COPY_TILE(st, k0p) do {                                               \
    _Pragma("unroll")                                                          \
    for (int i = 0; i < 4; i++) {                                              \
        const uint32_t* s = (ahisel[i] ? xh : xl) + asrc[i] + (k0p);           \
        cp_async16(STAGE_A(st) + adst[i], s, avalid[i]);                       \
    }                                                                          \
    _Pragma("unroll")                                                          \
    for (int i = 0; i < 2; i++) {                                              \
        const uint32_t* s = (bhisel[i] ? g_woh : g_wol) + bsrc[i] + (k0p);     \
        cp_async16(STAGE_B(st) + bdst[i], s, 16);                              \
    }                                                                          \
    asm volatile("cp.async.commit_group;" ::: "memory");                       \
} while (0)

    float acc[2][4][4];
#pragma unroll
    for (int i = 0; i < 2; i++)
#pragma unroll
        for (int j = 0; j < 4; j++)
#pragma unroll
            for (int k = 0; k < 4; k++) acc[i][j][k] = 0.f;

    COPY_TILE(0, 0);
    COPY_TILE(1, 16);

    for (int kt = 0; kt < 8; kt++) {
        if (kt < 6)
            asm volatile("cp.async.wait_group 1;" ::: "memory");
        else
            asm volatile("cp.async.wait_group 0;" ::: "memory");
        __syncthreads();

        if (kt < 6)
            COPY_TILE((kt + 2) % 3, (kt + 2) * 16);

        const uint32_t Ab = STAGE_A(kt % 3);
        const uint32_t Bb = STAGE_B(kt % 3);
#pragma unroll
        for (int ks = 0; ks < 2; ks++) {
            uint32_t ah[2][4], al[2][4], bh4[2][4], bl4[2][4];
#pragma unroll
            for (int ma = 0; ma < 2; ma++) {
                int row = wm + ma * 16 + (lg & 1) * 8 + li;
                int chh = ks * 2 + (lg >> 1);
                ldsm4(ah[ma], Ab + row * 128u + ((chh ^ (row & 7)) * 16u));
                ldsm4(al[ma], Ab + row * 128u + (((chh + 4) ^ (row & 7)) * 16u));
            }
#pragma unroll
            for (int p = 0; p < 2; p++) {
                int row = wn + p * 16 + (lg >> 1) * 8 + li;
                int chh = ks * 2 + (lg & 1);
                ldsm4(bh4[p], Bb + row * 128u + ((chh ^ (row & 7)) * 16u));
                ldsm4(bl4[p], Bb + row * 128u + (((chh + 4) ^ (row & 7)) * 16u));
            }
#pragma unroll
            for (int ma = 0; ma < 2; ma++)
#pragma unroll
                for (int p = 0; p < 2; p++) {
                    float* c0 = acc[ma][2 * p];
                    float* c1 = acc[ma][2 * p + 1];
                    mma_bf16(c0, ah[ma], bh4[p][0], bh4[p][1]);
                    mma_bf16(c0, ah[ma], bl4[p][0], bl4[p][1]);
                    mma_bf16(c0, al[ma], bh4[p][0], bh4[p][1]);
                    mma_bf16(c1, ah[ma], bh4[p][2], bh4[p][3]);
                    mma_bf16(c1, ah[ma], bl4[p][2], bl4[p][3]);
                    mma_bf16(c1, al[ma], bh4[p][2], bh4[p][3]);
                }
        }
    }
#undef COPY_TILE
#undef STAGE_A
#undef STAGE_B

#pragma unroll
    for (int ma = 0; ma < 2; ma++) {
        int gr0 = bm + wm + ma * 16 + gid;
        int gr1 = gr0 + 8;
#pragma unroll
        for (int na = 0; na < 4; na++) {
            int gc = bn + wn + na * 8 + tig * 2;
            float b0 = bo[gc], b1 = bo[gc + 1];
            float* c = acc[ma][na];
            if (gr0 < M)
                *(float2*)(out + (size_t)gr0 * D + gc) = make_float2(c[0] + b0, c[1] + b1);
            if (gr1 < M)
                *(float2*)(out + (size_t)gr1 * D + gc) = make_float2(c[2] + b0, c[3] + b1);
        }
    }
}

// ==================== CSR build ====================
__global__ void zero_kernel(int n)
{
    int i = blockIdx.x * blockDim.x + threadIdx.x;
    if (i < n) g_cnt[i] = 0;
}

__global__ void hist_kernel(const int* __restrict__ row, int E)
{
    int e = blockIdx.x * blockDim.x + threadIdx.x;
    if (e < E) atomicAdd(&g_cnt[row[e]], 1);
}

__global__ void scan_kernel(int n)
{
    __shared__ int warp_sums[32];
    __shared__ int carry;
    const int tid = threadIdx.x;
    const int lane = tid & 31;
    const int wid = tid >> 5;
    if (tid == 0) carry = 0;
    __syncthreads();
    for (int base = 0; base < n; base += 1024) {
        int i = base + tid;
        int v = (i < n) ? g_cnt[i] : 0;
        int x = v;
#pragma unroll
        for (int d = 1; d < 32; d <<= 1) {
            int y = __shfl_up_sync(0xffffffffu, x, d);
            if (lane >= d) x += y;
        }
        if (lane == 31) warp_sums[wid] = x;
        __syncthreads();
        if (wid == 0) {
            int sv = warp_sums[lane];
#pragma unroll
            for (int d = 1; d < 32; d <<= 1) {
                int y = __shfl_up_sync(0xffffffffu, sv, d);
                if (lane >= d) sv += y;
            }
            warp_sums[lane] = sv;
        }
        __syncthreads();
        int prefix = (wid > 0) ? warp_sums[wid - 1] : 0;
        int excl = x - v + prefix + carry;
        if (i < n) { g_ptr[i] = excl; g_fill[i] = excl; }
        int total = warp_sums[31];
        __syncthreads();
        if (tid == 0) carry = carry + total;
        __syncthreads();
    }
    if (tid == 0) g_ptr[n] = carry;
}

__global__ void scatter_kernel(const int* __restrict__ row,
                               const int* __restrict__ col, int E)
{
    int e = blockIdx.x * blockDim.x + threadIdx.x;
    if (e < E) {
        int p = atomicAdd(&g_fill[row[e]], 1);
        g_colbuf[p] = col[e];
    }
}

// ==================== attention: single pass, no max shift ====================
// exp(s)/sum(exp(s)) == exp(s-m)/sum(exp(s-m)); |s| <~ 6 so fp32 exp is safe.
__global__ __launch_bounds__(256) void attn_kernel(int nnodes)
{
    const int lane = threadIdx.x & 31;
    const int node = blockIdx.x * 8 + (threadIdx.x >> 5);
    if (node >= nnodes) return;
    const int start = g_ptr[node];
    const int end = g_ptr[node + 1];

    const int b4 = (lane >> 4) & 1;
    const int b3 = (lane >> 3) & 1;
    const int b2 = (lane >> 2) & 1;

    const float4* qp = (const float4*)(g_q + (size_t)node * D + lane * 8);
    float4 q0 = qp[0], q1 = qp[1];

    float acc[8];
#pragma unroll
    for (int i = 0; i < 8; i++) acc[i] = 0.f;
    float z = 0.f;   // sum of exp(s) for head myh (replicated x4)

    for (int base = start; base < end; base += 32) {
        int myj = 0;
        if (base + lane < end) myj = g_colbuf[base + lane];
        int cnt = min(32, end - base);
        for (int t = 0; t < cnt; t++) {
            int j = __shfl_sync(0xffffffffu, myj, t);
            uint4 kv = ((const uint4*)(g_kh + (size_t)j * DP))[lane];
            uint4 vv = ((const uint4*)(g_vh + (size_t)j * DP))[lane];
            float2 f0 = __half22float2(*(const __half2*)&kv.x);
            float2 f1 = __half22float2(*(const __half2*)&kv.y);
            float2 f2 = __half22float2(*(const __half2*)&kv.z);
            float2 f3 = __half22float2(*(const __half2*)&kv.w);
            float p0 = q0.x * f0.x, p1 = q0.y * f0.y, p2 = q0.z * f1.x, p3 = q0.w * f1.y;
            float p4 = q1.x * f2.x, p5 = q1.y * f2.y, p6 = q1.z * f3.x, p7 = q1.w * f3.y;
            float keep, send;
            keep = b4 ? p1 : p0; send = b4 ? p0 : p1;
            float tA0 = keep + __shfl_xor_sync(0xffffffffu, send, 16);
            keep = b4 ? p3 : p2; send = b4 ? p2 : p3;
            float tA1 = keep + __shfl_xor_sync(0xffffffffu, send, 16);
            keep = b4 ? p5 : p4; send = b4 ? p4 : p5;
            float tA2 = keep + __shfl_xor_sync(0xffffffffu, send, 16);
            keep = b4 ? p7 : p6; send = b4 ? p6 : p7;
            float tA3 = keep + __shfl_xor_sync(0xffffffffu, send, 16);
            keep = b3 ? tA1 : tA0; send = b3 ? tA0 : tA1;
            float tB0 = keep + __shfl_xor_sync(0xffffffffu, send, 8);
            keep = b3 ? tA3 : tA2; send = b3 ? tA2 : tA3;
            float tB1 = keep + __shfl_xor_sync(0xffffffffu, send, 8);
            keep = b2 ? tB1 : tB0; send = b2 ? tB0 : tB1;
            float s = keep + __shfl_xor_sync(0xffffffffu, send, 4);
            s += __shfl_xor_sync(0xffffffffu, s, 2);
            s += __shfl_xor_sync(0xffffffffu, s, 1);
            float w = __expf(s);   // head myh, replicated x4
            z += w;
            float2 g0 = __half22float2(*(const __half2*)&vv.x);
            float2 g1 = __half22float2(*(const __half2*)&vv.y);
            float2 g2 = __half22float2(*(const __half2*)&vv.z);
            float2 g3 = __half22float2(*(const __half2*)&vv.w);
            float vr[8] = {g0.x, g0.y, g1.x, g1.y, g2.x, g2.y, g3.x, g3.y};
#pragma unroll
            for (int i = 0; i < 8; i++) {
                float wi = __shfl_sync(0xffffffffu, w, OWNER(i));
                acc[i] = fmaf(wi, vr[i], acc[i]);
            }
        }
    }

    float out[8];
#pragma unroll
    for (int i = 0; i < 8; i++) {
        float zi = __shfl_sync(0xffffffffu, z, OWNER(i));
        out[i] = (zi > 0.f) ? (acc[i] / zi) : 0.f;
    }

    // bf16 splits for the output projection
    uint32_t hs[4], ls[4];
#pragma unroll
    for (int i = 0; i < 4; i++)
        split2_bf16(make_float2(out[2 * i], out[2 * i + 1]), hs[i], ls[i]);
    uint32_t* xo = g_xs + (size_t)node * DP + lane * 4;
    *(uint4*)xo = make_uint4(hs[0], hs[1], hs[2], hs[3]);
    *(uint4*)(xo + XSP) = make_uint4(ls[0], ls[1], ls[2], ls[3]);
}

// ==================== launch ====================
extern "C" void kernel_launch(void* const* d_in, const int* in_sizes, int n_in,
                              void* d_out, int out_size)
{
    const float* x  = (const float*)d_in[0];
    const int*   row = (const int*)d_in[1];
    const int*   col = (const int*)d_in[2];
    const float* Wq = (const float*)d_in[3];
    const float* bq = (const float*)d_in[4];
    const float* Wk = (const float*)d_in[5];
    const float* bk = (const float*)d_in[6];
    const float* Wv = (const float*)d_in[7];
    const float* bv = (const float*)d_in[8];
    const float* Wo = (const float*)d_in[9];
    const float* bo = (const float*)d_in[10];
    float* out = (float*)d_out;

    const int N = in_sizes[0] / D;
    const int E = in_sizes[1];
    const float scaling = 0.17677669529663687f; // 32^-0.5

    cudaFuncSetAttribute(gemm_qkv_kernel,
                         cudaFuncAttributeMaxDynamicSharedMemorySize, QKV_DSMEM);
    cudaFuncSetAttribute(gemm_o_kernel,
                         cudaFuncAttributeMaxDynamicSharedMemorySize, O_DSMEM);

    // CSR build
    zero_kernel<<<(N + 255) / 256, 256>>>(N);
    hist_kernel<<<(E + 255) / 256, 256>>>(row, E);
    scan_kernel<<<1, 1024>>>(N);
    scatter_kernel<<<(E + 255) / 256, 256>>>(row, col, E);

    // conversions
    dim3 wgrid((D * DP + 255) / 256, 4);
    convert_w_kernel<<<wgrid, 256>>>(Wq, Wk, Wv, Wo);
    convert_x_kernel<<<(N * DP + 255) / 256, 256>>>(x, N);

    // fused QKV projection (fp16 2-product)
    dim3 qkvgrid((N + 127) / 128, 12);
    gemm_qkv_kernel<<<qkvgrid, 256, QKV_DSMEM>>>(bq, bk, bv, N, scaling);

    // single-pass sparse attention
    attn_kernel<<<(N + 7) / 8, 256>>>(N);

    // output projection (bf16 3-product)
    dim3 ogrid((N + 127) / 128, 4);
    gemm_o_kernel<<<ogrid, 256, O_DSMEM>>>(bo, out, N);
}

// round 16
// speedup vs baseline: 2.4297x; 1.0201x over previous
#include <cuda_runtime.h>
#include <cuda_bf16.h>
#include <cuda_fp16.h>
#include <math.h>
#include <stdint.h>

#define D 256
#define H 8
#define MAXN 50000
#define MAXE 1600000
#define DP (D / 2)                 // 128 k-pairs per row
#define XSP ((size_t)MAXN * DP)    // elements per split half

// -------- scratch (no allocs allowed -> device globals) --------
__device__ __align__(16) float g_q[(size_t)MAXN * D];      // fp32 Q (scaled)
__device__ __align__(16) uint32_t g_kh[(size_t)MAXN * DP]; // K as half2
__device__ __align__(16) uint32_t g_vh[(size_t)MAXN * DP]; // V as half2
__device__ __align__(16) uint32_t g_s[2 * XSP];            // x fp16 splits (h|l planes)
__device__ __align__(16) uint32_t g_xs[2 * XSP];           // attn-out fp16 splits
__device__ int g_cnt[MAXN];
__device__ int g_ptr[MAXN + 1];
__device__ int g_fill[MAXN];
__device__ int g_colbuf[MAXE];
__device__ __align__(16) uint32_t g_wf16[4][D * DP];       // Wq/Wk/Wv/Wo^T [n][kpair] fp16

// owner lane of head i in the butterfly layout (b2=i>>2, b3=(i>>1)&1, b4=i&1)
#define OWNER(i) ((((i) & 1) << 4) | ((((i) >> 1) & 1) << 3) | ((((i) >> 2) & 1) << 2))

// 2-way fp16 split (h = rn(x), l = rn(x - h); h+l == x to ~2^-22)
__device__ __forceinline__ void split2_f16(float2 a, uint32_t& s1, uint32_t& s2)
{
    __half2 h1 = __floats2half2_rn(a.x, a.y);
    float2 f1 = __half22float2(h1);
    __half2 h2 = __floats2half2_rn(a.x - f1.x, a.y - f1.y);
    s1 = *(uint32_t*)&h1;
    s2 = *(uint32_t*)&h2;
}

__device__ __forceinline__ void mma_f16(
    float* c, const uint32_t* a, uint32_t b0, uint32_t b1)
{
    asm volatile(
        "mma.sync.aligned.m16n8k16.row.col.f32.f16.f16.f32 "
        "{%0,%1,%2,%3}, {%4,%5,%6,%7}, {%8,%9}, {%0,%1,%2,%3};\n"
        : "+f"(c[0]), "+f"(c[1]), "+f"(c[2]), "+f"(c[3])
        : "r"(a[0]), "r"(a[1]), "r"(a[2]), "r"(a[3]), "r"(b0), "r"(b1));
}

__device__ __forceinline__ void ldsm4(uint32_t* r, uint32_t addr)
{
    asm volatile("ldmatrix.sync.aligned.m8n8.x4.shared.b16 {%0,%1,%2,%3}, [%4];"
                 : "=r"(r[0]), "=r"(r[1]), "=r"(r[2]), "=r"(r[3]) : "r"(addr));
}

__device__ __forceinline__ uint32_t smem_u32(const void* p)
{
    uint32_t a;
    asm("{ .reg .u64 t; cvta.to.shared.u64 t, %1; cvt.u32.u64 %0, t; }" : "=r"(a) : "l"(p));
    return a;
}

__device__ __forceinline__ void cp_async16(uint32_t dst, const void* src, int szbytes)
{
    asm volatile("cp.async.cg.shared.global [%0], [%1], 16, %2;"
                 :: "r"(dst), "l"(src), "r"(szbytes) : "memory");
}

// ==================== conversion passes ====================
// x -> fp16 split planes in g_s
__global__ __launch_bounds__(256) void convert_x_kernel(
    const float* __restrict__ X, int M)
{
    int idx = blockIdx.x * blockDim.x + threadIdx.x;
    if (idx < M * DP) {
        float2 v = *(const float2*)(X + (size_t)idx * 2);
        uint32_t h, l;
        split2_f16(v, h, l);
        g_s[idx] = h;
        g_s[XSP + idx] = l;
    }
}

// blockIdx.y = widx: all four weights -> single fp16 plane each
__global__ __launch_bounds__(256) void convert_w_kernel(
    const float* __restrict__ Wq, const float* __restrict__ Wk,
    const float* __restrict__ Wv, const float* __restrict__ Wo)
{
    int widx = blockIdx.y;
    const float* W = (widx == 0) ? Wq : (widx == 1) ? Wk : (widx == 2) ? Wv : Wo;
    int slot = blockIdx.x * blockDim.x + threadIdx.x;
    if (slot < D * DP) {
        int n = slot & (D - 1);
        int kp = slot >> 8;
        float a0 = W[(size_t)(2 * kp) * D + n];
        float a1 = W[(size_t)(2 * kp + 1) * D + n];
        __half2 hv = __floats2half2_rn(a0, a1);
        g_wf16[widx][(size_t)n * DP + kp] = *(uint32_t*)&hv;
    }
}

// ==================== unified fp16 2-product GEMM, 5-stage cp.async ====================
// mode 0: fused QKV (grid.y = 12; widx = y>>2, bn = (y&3)*64); A splits in g_s.
//   widx 0 -> fp32 g_q (alpha=scaling), widx 1 -> g_kh half2, widx 2 -> g_vh half2.
// mode 1: out-projection (grid.y = 4; widx = 3); A splits in g_xs; C = out_ext fp32.
// A: (ah + al) * Wh == a * Wh exactly in the fp32 accumulator.
// SMEM/stage: A 16 KB (128 rows x 128B XOR-swizzled), B 5 KB (64 rows x 80B,
// 20r mod 32 -> conflict-free ldsm without swizzle). 5 stages = 107520 B.
#define GEMM_DSMEM (5 * (16384 + 5120))
__global__ __launch_bounds__(256) void gemm_f16_kernel(
    int mode,
    const float* __restrict__ bq, const float* __restrict__ bk,
    const float* __restrict__ bv, const float* __restrict__ bo,
    float* __restrict__ out_ext, int M, float scaling)
{
    extern __shared__ __align__(16) char dynsm[];
    const uint32_t sbase = smem_u32(dynsm);

    int widx, bn;
    const float* bias;
    float alpha = 1.f;
    const uint32_t *xh, *xl;
    if (mode == 0) {
        widx = blockIdx.y >> 2;
        bn = (blockIdx.y & 3) * 64;
        xh = g_s;
        xl = g_s + XSP;
        bias = (widx == 0) ? bq : (widx == 1) ? bk : bv;
        if (widx == 0) alpha = scaling;
    } else {
        widx = 3;
        bn = blockIdx.y * 64;
        xh = g_xs;
        xl = g_xs + XSP;
        bias = bo;
    }
    const uint32_t* __restrict__ WT = g_wf16[widx];

    const int tid = threadIdx.x;
    const int lane = tid & 31;
    const int warp = tid >> 5;
    const int lg = lane >> 3;
    const int li = lane & 7;
    const int gid = lane >> 2;
    const int tig = lane & 3;
    const int wm = (warp & 3) * 32;
    const int wn = (warp >> 2) * 32;
    const int bm = blockIdx.x * 128;

    // A: 4 chunks/thread (128 rows x 8 chunks of 16B: hi 0-3 | lo 4-7, XOR swizzle)
    uint32_t adst[4]; size_t asrc[4]; int avalid[4], ahisel[4];
#pragma unroll
    for (int i = 0; i < 4; i++) {
        int c = tid + i * 256;
        int r = c >> 3, ch = c & 7;
        adst[i] = r * 128u + ((ch ^ (r & 7)) * 16u);
        int gr = bm + r;
        avalid[i] = (gr < M) ? 16 : 0;
        asrc[i] = (size_t)((gr < M) ? gr : 0) * DP + (ch & 3) * 4;
        ahisel[i] = (ch < 4);
    }
    // B: 1 chunk/thread (64 rows x 4 chunks of 16B, stride 80)
    const int br = tid >> 2;
    const int bch = tid & 3;
    const uint32_t bdst = br * 80u + bch * 16u;
    const size_t bsrc = (size_t)(bn + br) * DP + bch * 4;

#define STAGE_A(st) (sbase + (uint32_t)(st) * 16384u)
#define STAGE_B(st) (sbase + 81920u + (uint32_t)(st) * 5120u)
#define COPY_TILE(st, k0p) do {                                               \
    _Pragma("unroll")                                                          \
    for (int i = 0; i < 4; i++) {                                              \
        const uint32_t* s = (ahisel[i] ? xh : xl) + asrc[i] + (k0p);           \
        cp_async16(STAGE_A(st) + adst[i], s, avalid[i]);                       \
    }                                                                          \
    cp_async16(STAGE_B(st) + bdst, WT + bsrc + (k0p), 16);                     \
    asm volatile("cp.async.commit_group;" ::: "memory");                       \
} while (0)

    float acc[2][4][4];
#pragma unroll
    for (int i = 0; i < 2; i++)
#pragma unroll
        for (int j = 0; j < 4; j++)
#pragma unroll
            for (int k = 0; k < 4; k++) acc[i][j][k] = 0.f;

    COPY_TILE(0, 0);
    COPY_TILE(1, 16);
    COPY_TILE(2, 32);
    COPY_TILE(3, 48);

#pragma unroll
    for (int kt = 0; kt < 8; kt++) {
        // drain until tile kt has landed: allow min(3, 7-kt) groups outstanding
        if (kt < 5)      asm volatile("cp.async.wait_group 3;" ::: "memory");
        else if (kt == 5) asm volatile("cp.async.wait_group 2;" ::: "memory");
        else if (kt == 6) asm volatile("cp.async.wait_group 1;" ::: "memory");
        else              asm volatile("cp.async.wait_group 0;" ::: "memory");
        __syncthreads();   // all warps done with tile kt-1 (stage being refilled)

        if (kt < 4)
            COPY_TILE((kt + 4) % 5, (kt + 4) * 16);

        const uint32_t Ab = STAGE_A(kt % 5);
        const uint32_t Bb = STAGE_B(kt % 5);
#pragma unroll
        for (int ks = 0; ks < 2; ks++) {
            uint32_t ah[2][4], al[2][4], bb[2][4];
#pragma unroll
            for (int ma = 0; ma < 2; ma++) {
                int row = wm + ma * 16 + (lg & 1) * 8 + li;
                int chh = ks * 2 + (lg >> 1);
                ldsm4(ah[ma], Ab + row * 128u + ((chh ^ (row & 7)) * 16u));
                ldsm4(al[ma], Ab + row * 128u + (((chh + 4) ^ (row & 7)) * 16u));
            }
#pragma unroll
            for (int p = 0; p < 2; p++) {
                int row = wn + p * 16 + (lg >> 1) * 8 + li;
                int chh = ks * 2 + (lg & 1);
                ldsm4(bb[p], Bb + row * 80u + chh * 16u);
            }
#pragma unroll
            for (int ma = 0; ma < 2; ma++)
#pragma unroll
                for (int p = 0; p < 2; p++) {
                    float* c0 = acc[ma][2 * p];
                    float* c1 = acc[ma][2 * p + 1];
                    mma_f16(c0, ah[ma], bb[p][0], bb[p][1]);
                    mma_f16(c0, al[ma], bb[p][0], bb[p][1]);
                    mma_f16(c1, ah[ma], bb[p][2], bb[p][3]);
                    mma_f16(c1, al[ma], bb[p][2], bb[p][3]);
                }
        }
    }
#undef COPY_TILE
#undef STAGE_A
#undef STAGE_B

    // epilogue: widx 0 -> fp32 g_q (scaled); 1/2 -> fp16 tables; 3 -> fp32 out
#pragma unroll
    for (int ma = 0; ma < 2; ma++) {
        int gr0 = bm + wm + ma * 16 + gid;
        int gr1 = gr0 + 8;
#pragma unroll
        for (int na = 0; na < 4; na++) {
            int gc = bn + wn + na * 8 + tig * 2;
            float b0 = bias[gc], b1 = bias[gc + 1];
            float* c = acc[ma][na];
            if (widx == 0 || widx == 3) {
                float* C = (widx == 0) ? g_q : out_ext;
                if (gr0 < M)
                    *(float2*)(C + (size_t)gr0 * D + gc) =
                        make_float2((c[0] + b0) * alpha, (c[1] + b1) * alpha);
                if (gr1 < M)
                    *(float2*)(C + (size_t)gr1 * D + gc) =
                        make_float2((c[2] + b0) * alpha, (c[3] + b1) * alpha);
            } else {
                uint32_t* T = (widx == 1) ? g_kh : g_vh;
                if (gr0 < M) {
                    __half2 hv = __floats2half2_rn(c[0] + b0, c[1] + b1);
                    T[(size_t)gr0 * DP + (gc >> 1)] = *(uint32_t*)&hv;
                }
                if (gr1 < M) {
                    __half2 hv = __floats2half2_rn(c[2] + b0, c[3] + b1);
                    T[(size_t)gr1 * DP + (gc >> 1)] = *(uint32_t*)&hv;
                }
            }
        }
    }
}

// ==================== CSR build ====================
__global__ void zero_kernel(int n)
{
    int i = blockIdx.x * blockDim.x + threadIdx.x;
    if (i < n) g_cnt[i] = 0;
}

__global__ void hist_kernel(const int* __restrict__ row, int E)
{
    int e = blockIdx.x * blockDim.x + threadIdx.x;
    if (e < E) atomicAdd(&g_cnt[row[e]], 1);
}

__global__ void scan_kernel(int n)
{
    __shared__ int warp_sums[32];
    __shared__ int carry;
    const int tid = threadIdx.x;
    const int lane = tid & 31;
    const int wid = tid >> 5;
    if (tid == 0) carry = 0;
    __syncthreads();
    for (int base = 0; base < n; base += 1024) {
        int i = base + tid;
        int v = (i < n) ? g_cnt[i] : 0;
        int x = v;
#pragma unroll
        for (int d = 1; d < 32; d <<= 1) {
            int y = __shfl_up_sync(0xffffffffu, x, d);
            if (lane >= d) x += y;
        }
        if (lane == 31) warp_sums[wid] = x;
        __syncthreads();
        if (wid == 0) {
            int sv = warp_sums[lane];
#pragma unroll
            for (int d = 1; d < 32; d <<= 1) {
                int y = __shfl_up_sync(0xffffffffu, sv, d);
                if (lane >= d) sv += y;
            }
            warp_sums[lane] = sv;
        }
        __syncthreads();
        int prefix = (wid > 0) ? warp_sums[wid - 1] : 0;
        int excl = x - v + prefix + carry;
        if (i < n) { g_ptr[i] = excl; g_fill[i] = excl; }
        int total = warp_sums[31];
        __syncthreads();
        if (tid == 0) carry = carry + total;
        __syncthreads();
    }
    if (tid == 0) g_ptr[n] = carry;
}

__global__ void scatter_kernel(const int* __restrict__ row,
                               const int* __restrict__ col, int E)
{
    int e = blockIdx.x * blockDim.x + threadIdx.x;
    if (e < E) {
        int p = atomicAdd(&g_fill[row[e]], 1);
        g_colbuf[p] = col[e];
    }
}

// ==================== attention: single pass, no max shift ====================
// exp(s)/sum(exp(s)) == exp(s-m)/sum(exp(s-m)); |s| <~ 6 so fp32 exp is safe.
__global__ __launch_bounds__(256) void attn_kernel(int nnodes)
{
    const int lane = threadIdx.x & 31;
    const int node = blockIdx.x * 8 + (threadIdx.x >> 5);
    if (node >= nnodes) return;
    const int start = g_ptr[node];
    const int end = g_ptr[node + 1];

    const int b4 = (lane >> 4) & 1;
    const int b3 = (lane >> 3) & 1;
    const int b2 = (lane >> 2) & 1;

    const float4* qp = (const float4*)(g_q + (size_t)node * D + lane * 8);
    float4 q0 = qp[0], q1 = qp[1];

    float acc[8];
#pragma unroll
    for (int i = 0; i < 8; i++) acc[i] = 0.f;
    float z = 0.f;   // sum of exp(s) for head myh (replicated x4)

    for (int base = start; base < end; base += 32) {
        int myj = 0;
        if (base + lane < end) myj = g_colbuf[base + lane];
        int cnt = min(32, end - base);
        for (int t = 0; t < cnt; t++) {
            int j = __shfl_sync(0xffffffffu, myj, t);
            uint4 kv = ((const uint4*)(g_kh + (size_t)j * DP))[lane];
            uint4 vv = ((const uint4*)(g_vh + (size_t)j * DP))[lane];
            float2 f0 = __half22float2(*(const __half2*)&kv.x);
            float2 f1 = __half22float2(*(const __half2*)&kv.y);
            float2 f2 = __half22float2(*(const __half2*)&kv.z);
            float2 f3 = __half22float2(*(const __half2*)&kv.w);
            float p0 = q0.x * f0.x, p1 = q0.y * f0.y, p2 = q0.z * f1.x, p3 = q0.w * f1.y;
            float p4 = q1.x * f2.x, p5 = q1.y * f2.y, p6 = q1.z * f3.x, p7 = q1.w * f3.y;
            float keep, send;
            keep = b4 ? p1 : p0; send = b4 ? p0 : p1;
            float tA0 = keep + __shfl_xor_sync(0xffffffffu, send, 16);
            keep = b4 ? p3 : p2; send = b4 ? p2 : p3;
            float tA1 = keep + __shfl_xor_sync(0xffffffffu, send, 16);
            keep = b4 ? p5 : p4; send = b4 ? p4 : p5;
            float tA2 = keep + __shfl_xor_sync(0xffffffffu, send, 16);
            keep = b4 ? p7 : p6; send = b4 ? p6 : p7;
            float tA3 = keep + __shfl_xor_sync(0xffffffffu, send, 16);
            keep = b3 ? tA1 : tA0; send = b3 ? tA0 : tA1;
            float tB0 = keep + __shfl_xor_sync(0xffffffffu, send, 8);
            keep = b3 ? tA3 : tA2; send = b3 ? tA2 : tA3;
            float tB1 = keep + __shfl_xor_sync(0xffffffffu, send, 8);
            keep = b2 ? tB1 : tB0; send = b2 ? tB0 : tB1;
            float s = keep + __shfl_xor_sync(0xffffffffu, send, 4);
            s += __shfl_xor_sync(0xffffffffu, s, 2);
            s += __shfl_xor_sync(0xffffffffu, s, 1);
            float w = __expf(s);   // head myh, replicated x4
            z += w;
            float2 g0 = __half22float2(*(const __half2*)&vv.x);
            float2 g1 = __half22float2(*(const __half2*)&vv.y);
            float2 g2 = __half22float2(*(const __half2*)&vv.z);
            float2 g3 = __half22float2(*(const __half2*)&vv.w);
            float vr[8] = {g0.x, g0.y, g1.x, g1.y, g2.x, g2.y, g3.x, g3.y};
#pragma unroll
            for (int i = 0; i < 8; i++) {
                float wi = __shfl_sync(0xffffffffu, w, OWNER(i));
                acc[i] = fmaf(wi, vr[i], acc[i]);
            }
        }
    }

    float out[8];
#pragma unroll
    for (int i = 0; i < 8; i++) {
        float zi = __shfl_sync(0xffffffffu, z, OWNER(i));
        out[i] = (zi > 0.f) ? (acc[i] / zi) : 0.f;
    }

    // fp16 splits for the output projection (h+l reconstruction exact)
    uint32_t hs[4], ls[4];
#pragma unroll
    for (int i = 0; i < 4; i++)
        split2_f16(make_float2(out[2 * i], out[2 * i + 1]), hs[i], ls[i]);
    uint32_t* xo = g_xs + (size_t)node * DP + lane * 4;
    *(uint4*)xo = make_uint4(hs[0], hs[1], hs[2], hs[3]);
    *(uint4*)(xo + XSP) = make_uint4(ls[0], ls[1], ls[2], ls[3]);
}

// ==================== launch ====================
extern "C" void kernel_launch(void* const* d_in, const int* in_sizes, int n_in,
                              void* d_out, int out_size)
{
    const float* x  = (const float*)d_in[0];
    const int*   row = (const int*)d_in[1];
    const int*   col = (const int*)d_in[2];
    const float* Wq = (const float*)d_in[3];
    const float* bq = (const float*)d_in[4];
    const float* Wk = (const float*)d_in[5];
    const float* bk = (const float*)d_in[6];
    const float* Wv = (const float*)d_in[7];
    const float* bv = (const float*)d_in[8];
    const float* Wo = (const float*)d_in[9];
    const float* bo = (const float*)d_in[10];
    float* out = (float*)d_out;

    const int N = in_sizes[0] / D;
    const int E = in_sizes[1];
    const float scaling = 0.17677669529663687f; // 32^-0.5

    cudaFuncSetAttribute(gemm_f16_kernel,
                         cudaFuncAttributeMaxDynamicSharedMemorySize, GEMM_DSMEM);

    // CSR build
    zero_kernel<<<(N + 255) / 256, 256>>>(N);
    hist_kernel<<<(E + 255) / 256, 256>>>(row, E);
    scan_kernel<<<1, 1024>>>(N);
    scatter_kernel<<<(E + 255) / 256, 256>>>(row, col, E);

    // conversions
    dim3 wgrid((D * DP + 255) / 256, 4);
    convert_w_kernel<<<wgrid, 256>>>(Wq, Wk, Wv, Wo);
    convert_x_kernel<<<(N * DP + 255) / 256, 256>>>(x, N);

    // fused QKV projection (fp16 2-product, 5-stage pipeline)
    dim3 qkvgrid((N + 127) / 128, 12);
    gemm_f16_kernel<<<qkvgrid, 256, GEMM_DSMEM>>>(0, bq, bk, bv, bo, nullptr, N, scaling);

    // single-pass sparse attention (epilogue writes fp16 splits to g_xs)
    attn_kernel<<<(N + 7) / 8, 256>>>(N);

    // output projection (fp16 2-product, same kernel)
    dim3 ogrid((N + 127) / 128, 4);
    gemm_f16_kernel<<<ogrid, 256, GEMM_DSMEM>>>(1, bq, bk, bv, bo, out, N, scaling);
}